// round 13
// baseline (speedup 1.0000x reference)
#include <cuda_runtime.h>
#include <math.h>
#include <stdint.h>

#define B_ 4
#define S_ 2048
#define D_ 1024
#define GC_ 64
#define EPS_ 1e-6f

// GEMM tiling
#define BM 128
#define BN 128
#define BK 32
#define ST_ 3
#define ASTRIDE 36                        // 32 + 4 pad floats
#define STAGE_F (2 * 128 * ASTRIDE)       // floats per stage (A + B)
#define STAGE_BYTES (STAGE_F * 4)
#define SMEM_DYN (ST_ * STAGE_BYTES)

#define BSD ((size_t)B_ * S_ * D_)

// ---------------- scratch (device globals: allocation-guard safe) ----------------
static __device__ __align__(256) float g_Xt [BSD];          // tf32-rounded x
static __device__ __align__(256) float g_QKV[3 * BSD];      // Q | K | V
static __device__ __align__(256) float g_Vt [BSD];
static __device__ __align__(256) float g_Cv [BSD];
static __device__ __align__(256) float g_Ao [BSD];
static __device__ __align__(256) float g_Sc [(size_t)B_*S_*S_];
static __device__ __align__(256) float g_Wt [(size_t)4*D_*D_];  // Wq^T|Wk^T|Wv^T|Wo^T
static __device__ __align__(256) float g_bias[3 * D_];

// ---------------- helpers ----------------
__device__ __forceinline__ uint32_t smem_u32(const void* p) {
    uint32_t a;
    asm("{ .reg .u64 t; cvta.to.shared.u64 t, %1; cvt.u32.u64 %0, t; }" : "=r"(a) : "l"(p));
    return a;
}
__device__ __forceinline__ float to_tf32(float x) {
    uint32_t o;
    asm("cvt.rna.tf32.f32 %0, %1;" : "=r"(o) : "f"(x));
    return __uint_as_float(o);
}
__device__ __forceinline__ void cpa16(uint32_t s, const float* g) {
    asm volatile("cp.async.cg.shared.global [%0], [%1], 16;" :: "r"(s), "l"(g));
}
#define CP_COMMIT() asm volatile("cp.async.commit_group;" ::: "memory")
#define CP_WAIT1()  asm volatile("cp.async.wait_group 1;"  ::: "memory")

__device__ __forceinline__ void ldsm4(uint32_t* r, uint32_t a) {
    asm volatile("ldmatrix.sync.aligned.m8n8.x4.shared.b16 {%0,%1,%2,%3}, [%4];"
        : "=r"(r[0]), "=r"(r[1]), "=r"(r[2]), "=r"(r[3]) : "r"(a));
}
__device__ __forceinline__ void mma_tf32(float* c, const uint32_t* a, const uint32_t* b) {
    asm volatile(
        "mma.sync.aligned.m16n8k8.row.col.f32.tf32.tf32.f32 "
        "{%0,%1,%2,%3}, {%4,%5,%6,%7}, {%8,%9}, {%0,%1,%2,%3};"
        : "+f"(c[0]), "+f"(c[1]), "+f"(c[2]), "+f"(c[3])
        : "r"(a[0]), "r"(a[1]), "r"(a[2]), "r"(a[3]), "r"(b[0]), "r"(b[1]));
}

// ---------------- mma.sync tf32 GEMM: C = alpha*A@B^T (+bias) (+res) ----------------
// A [M,K] row-major, B [N,K] row-major (pre-rounded tf32).
// 128x128x32 CTA tile, 128 threads, 4 warps (2m x 2n), warp tile 64x64.
// 3-stage cp.async ring, 2 CTAs/SM, ONE barrier per k-tile.
// SPLIT: output columns 1024-segmented into 3 consecutive [M,1024] buffers.
template <int CVT, int SPLIT>
__global__ void __launch_bounds__(128, 2) mma_gemm(
    const float* __restrict__ A, const float* __restrict__ B,
    const float* __restrict__ bias, const float* __restrict__ res,
    float* __restrict__ C, int M, int N, int Kd,
    long long sA, long long sB, long long sC, float alpha)
{
    extern __shared__ __align__(128) float smemf[];
    const uint32_t smem_base = smem_u32(smemf);

    const int t    = threadIdx.x;
    const int wid  = t >> 5;
    const int lane = t & 31;
    const int g    = lane >> 2;
    const int q    = lane & 3;
    const int wm   = wid & 1;
    const int wn   = wid >> 1;
    const int m0 = blockIdx.y * BM, n0 = blockIdx.x * BN;

    const float* Ab = A + (long long)blockIdx.z * sA;
    const float* Bb = B + (long long)blockIdx.z * sB;
    const float* Rb = res ? res + (long long)blockIdx.z * sC : nullptr;

    float acc[4][8][4];
    #pragma unroll
    for (int i = 0; i < 4; i++)
        #pragma unroll
        for (int j = 0; j < 8; j++)
            #pragma unroll
            for (int k = 0; k < 4; k++) acc[i][j][k] = 0.f;

    const int nk = Kd / BK;

    auto load_stage = [&](int j, int s) {
        const int k0 = j * BK;
        const uint32_t sb = smem_base + (uint32_t)s * STAGE_BYTES;
        #pragma unroll
        for (int i = 0; i < 8; i++) {
            int idx = t + i * 128;
            int row = idx >> 3, c4 = idx & 7;
            cpa16(sb + (uint32_t)(row * ASTRIDE + c4 * 4) * 4,
                  Ab + (long long)(m0 + row) * Kd + k0 + c4 * 4);
        }
        #pragma unroll
        for (int i = 0; i < 8; i++) {
            int idx = t + i * 128;
            int row = idx >> 3, c4 = idx & 7;
            cpa16(sb + (uint32_t)(128 * ASTRIDE + row * ASTRIDE + c4 * 4) * 4,
                  Bb + (long long)(n0 + row) * Kd + k0 + c4 * 4);
        }
    };

    load_stage(0, 0); CP_COMMIT();
    load_stage(1, 1); CP_COMMIT();

    const int arow = wm * 64;
    const int bcol = wn * 64;

    // ldmatrix lane address offsets
    const int i8 = lane & 7, qd = lane >> 3;
    uint32_t offA[4], offB[4];
    #pragma unroll
    for (int mf = 0; mf < 4; mf++) {
        int row = arow + mf * 16 + i8 + (qd & 1) * 8;
        offA[mf] = (uint32_t)(row * ASTRIDE + (qd >> 1) * 4) * 4;
    }
    #pragma unroll
    for (int p = 0; p < 4; p++) {
        int row = bcol + p * 16 + i8 + (qd >> 1) * 8;
        offB[p] = (uint32_t)(row * ASTRIDE + (qd & 1) * 4) * 4;
    }

    int s = 0;
    for (int it = 0; it < nk; it++) {
        CP_WAIT1();
        __syncthreads();            // all warps done with stage (s+2)%3's previous use
        const int j = it + 2;
        if (j < nk) {
            int sn = s + 2; if (sn >= ST_) sn -= ST_;
            load_stage(j, sn);
        }
        CP_COMMIT();

        const uint32_t sAb = smem_base + (uint32_t)s * STAGE_BYTES;
        const uint32_t sBb = sAb + (uint32_t)(128 * ASTRIDE * 4);

        #pragma unroll
        for (int ks = 0; ks < 4; ks++) {
            const uint32_t kb = (uint32_t)(ks * 8 * 4);
            uint32_t a[4][4], b[8][2];
            #pragma unroll
            for (int mf = 0; mf < 4; mf++) ldsm4(a[mf], sAb + offA[mf] + kb);
            #pragma unroll
            for (int p = 0; p < 4; p++) ldsm4(&b[2 * p][0], sBb + offB[p] + kb);
            #pragma unroll
            for (int mf = 0; mf < 4; mf++)
                #pragma unroll
                for (int nf = 0; nf < 8; nf++)
                    mma_tf32(acc[mf][nf], a[mf], b[nf]);
        }
        if (++s == ST_) s = 0;
    }

    // epilogue
    float* Cb;
    int colBase, rowStride;
    if (SPLIT) {
        Cb = C + (long long)(n0 >> 10) * (long long)(B_ * (size_t)S_ * D_);
        colBase = n0 & 1023;
        rowStride = 1024;
    } else {
        Cb = C + (long long)blockIdx.z * sC;
        colBase = n0;
        rowStride = N;
    }

    #pragma unroll
    for (int mf = 0; mf < 4; mf++) {
        #pragma unroll
        for (int nf = 0; nf < 8; nf++) {
            const int row  = m0 + arow + mf * 16 + g;
            const int colG = n0 + bcol + nf * 8 + q * 2;
            const int col  = colBase + bcol + nf * 8 + q * 2;
            float bx = 0.f, by = 0.f;
            if (bias) { bx = bias[colG]; by = bias[colG + 1]; }
            #pragma unroll
            for (int h = 0; h < 2; h++) {
                const int r = row + h * 8;
                float vx = acc[mf][nf][h * 2 + 0] * alpha + bx;
                float vy = acc[mf][nf][h * 2 + 1] * alpha + by;
                if (Rb) {
                    float2 rv = *(const float2*)&Rb[(long long)r * rowStride + col];
                    vx += rv.x; vy += rv.y;
                }
                if (CVT) { vx = to_tf32(vx); vy = to_tf32(vy); }
                float2 v; v.x = vx; v.y = vy;
                *(float2*)&Cb[(long long)r * rowStride + col] = v;
            }
        }
    }
}

// ---------------- convert x -> tf32 + pack bias (single launch) ----------------
__global__ void __launch_bounds__(256) convert_pack_kernel(
    const float* __restrict__ in, float* __restrict__ out, int n4,
    const float* __restrict__ bq, const float* __restrict__ bv,
    float* __restrict__ biasOut)
{
    int i = blockIdx.x * 256 + threadIdx.x;
    if (blockIdx.x == gridDim.x - 1) {
        // last block packs bias [bq | 0 | bv]
        for (int k = threadIdx.x; k < 3 * D_; k += 256)
            biasOut[k] = (k < D_) ? bq[k] : ((k < 2 * D_) ? 0.f : bv[k - 2 * D_]);
        return;
    }
    if (i < n4) {
        float4 v = ((const float4*)in)[i];
        v.x = to_tf32(v.x); v.y = to_tf32(v.y);
        v.z = to_tf32(v.z); v.w = to_tf32(v.w);
        ((float4*)out)[i] = v;
    }
}

__global__ void __launch_bounds__(256) transpose_kernel(
    const float* __restrict__ in, float* __restrict__ out,
    int R, int C, long long sIn, long long sOut)
{
    __shared__ float tile[32][33];
    in  += (long long)blockIdx.z * sIn;
    out += (long long)blockIdx.z * sOut;
    const int tx = threadIdx.x & 31, ty = threadIdx.x >> 5;
    const int c0 = blockIdx.x * 32, r0 = blockIdx.y * 32;
    #pragma unroll
    for (int j = 0; j < 4; j++)
        tile[ty + j * 8][tx] = in[(long long)(r0 + ty + j * 8) * C + c0 + tx];
    __syncthreads();
    #pragma unroll
    for (int j = 0; j < 4; j++)
        out[(long long)(c0 + ty + j * 8) * R + r0 + tx] = to_tf32(tile[tx][ty + j * 8]);
}

// ---------------- reductions ----------------
__device__ __forceinline__ float warpSum(float v) {
    #pragma unroll
    for (int o = 16; o > 0; o >>= 1) v += __shfl_xor_sync(0xffffffffu, v, o);
    return v;
}
__device__ __forceinline__ float warpMax(float v) {
    #pragma unroll
    for (int o = 16; o > 0; o >>= 1) v = fmaxf(v, __shfl_xor_sync(0xffffffffu, v, o));
    return v;
}
__device__ __forceinline__ float blockSum(float v, float* red) {
    int t = threadIdx.x, lane = t & 31, w = t >> 5;
    v = warpSum(v);
    if (lane == 0) red[w] = v;
    __syncthreads();
    if (w == 0) {
        float x = (lane < 8) ? red[lane] : 0.f;
        x = warpSum(x);
        if (lane == 0) red[0] = x;
    }
    __syncthreads();
    float r = red[0];
    __syncthreads();
    return r;
}
__device__ __forceinline__ float blockMax(float v, float* red) {
    int t = threadIdx.x, lane = t & 31, w = t >> 5;
    v = warpMax(v);
    if (lane == 0) red[w] = v;
    __syncthreads();
    if (w == 0) {
        float x = (lane < 8) ? red[lane] : -1e30f;
        x = warpMax(x);
        if (lane == 0) red[0] = x;
    }
    __syncthreads();
    float r = red[0];
    __syncthreads();
    return r;
}

// ---------------- grouped conv1d (K=3, pad=1) + LayerNorm ----------------
__global__ void __launch_bounds__(256) conv_ln_kernel(
    const float* __restrict__ x, const float* __restrict__ cw,
    const float* __restrict__ cb, const float* __restrict__ gamma,
    const float* __restrict__ beta)
{
    __shared__ float xs[6][D_];
    __shared__ float red[32];

    const int t  = threadIdx.x;
    const int s0 = blockIdx.x * 4;
    const int b  = blockIdx.y;
    const float* xb = x + (size_t)b * S_ * D_;

    #pragma unroll
    for (int r = 0; r < 6; r++) {
        int sr = s0 - 1 + r;
        if (sr >= 0 && sr < S_) {
            for (int i = t; i < D_; i += 256) xs[r][i] = xb[(size_t)sr * D_ + i];
        } else {
            for (int i = t; i < D_; i += 256) xs[r][i] = 0.f;
        }
    }
    __syncthreads();

    float acc[4][4];
    #pragma unroll
    for (int dd = 0; dd < 4; dd++) {
        const int d  = t * 4 + dd;
        const int gb = (d >> 6) << 6;
        const float* wp = cw + (size_t)d * GC_ * 3;
        float a0 = cb[d], a1 = a0, a2 = a0, a3 = a0;
        #pragma unroll 8
        for (int c = 0; c < GC_; c++) {
            float w0 = wp[c * 3 + 0], w1 = wp[c * 3 + 1], w2 = wp[c * 3 + 2];
            float x0 = xs[0][gb + c], x1 = xs[1][gb + c], x2 = xs[2][gb + c];
            float x3 = xs[3][gb + c], x4 = xs[4][gb + c], x5 = xs[5][gb + c];
            a0 += w0 * x0 + w1 * x1 + w2 * x2;
            a1 += w0 * x1 + w1 * x2 + w2 * x3;
            a2 += w0 * x2 + w1 * x3 + w2 * x4;
            a3 += w0 * x3 + w1 * x4 + w2 * x5;
        }
        acc[dd][0] = a0; acc[dd][1] = a1; acc[dd][2] = a2; acc[dd][3] = a3;
    }

    const float4 gv = *(const float4*)&gamma[t * 4];
    const float4 bvv = *(const float4*)&beta[t * 4];
    const float gvl[4] = {gv.x, gv.y, gv.z, gv.w};
    const float bvl[4] = {bvv.x, bvv.y, bvv.z, bvv.w};

    for (int p = 0; p < 4; p++) {
        float s = acc[0][p] + acc[1][p] + acc[2][p] + acc[3][p];
        float mean = blockSum(s, red) * (1.f / D_);
        float sq = 0.f;
        #pragma unroll
        for (int dd = 0; dd < 4; dd++) { float dl = acc[dd][p] - mean; sq += dl * dl; }
        float var = blockSum(sq, red) * (1.f / (D_ - 1));
        float inv = 1.f / (sqrtf(var) + EPS_);
        float* out = g_Cv + ((size_t)b * S_ + s0 + p) * D_;
        float4 ov;
        ov.x = gvl[0] * (acc[0][p] - mean) * inv + bvl[0];
        ov.y = gvl[1] * (acc[1][p] - mean) * inv + bvl[1];
        ov.z = gvl[2] * (acc[2][p] - mean) * inv + bvl[2];
        ov.w = gvl[3] * (acc[3][p] - mean) * inv + bvl[3];
        *(float4*)&out[t * 4] = ov;
    }
}

// ---------------- row softmax (writes tf32-rounded probs) ----------------
__global__ void __launch_bounds__(256) softmax_kernel()
{
    __shared__ float red[32];
    const int t = threadIdx.x;
    float* row = g_Sc + ((size_t)blockIdx.y * S_ + blockIdx.x) * S_;

    float v[8];
    float m = -1e30f;
    #pragma unroll
    for (int j = 0; j < 8; j++) { v[j] = row[t + j * 256]; m = fmaxf(m, v[j]); }
    m = blockMax(m, red);

    float sum = 0.f;
    #pragma unroll
    for (int j = 0; j < 8; j++) { v[j] = __expf(v[j] - m); sum += v[j]; }
    sum = blockSum(sum, red);
    float inv = 1.f / sum;
    #pragma unroll
    for (int j = 0; j < 8; j++) row[t + j * 256] = to_tf32(v[j] * inv);
}

// ---------------- combined = LN(conv_ln + attn_out) -> g_Cv (tf32-rounded) ------
__global__ void __launch_bounds__(256) add_ln_kernel(
    const float* __restrict__ gamma, const float* __restrict__ beta)
{
    __shared__ float red[32];
    const int t = threadIdx.x;
    const size_t row = ((size_t)blockIdx.y * S_ + blockIdx.x) * D_;

    float v[4];
    float s = 0.f;
    #pragma unroll
    for (int j = 0; j < 4; j++) {
        int i = t + j * 256;
        v[j] = g_Cv[row + i] + g_Ao[row + i];
        s += v[j];
    }
    float mean = blockSum(s, red) * (1.f / D_);
    float sq = 0.f;
    #pragma unroll
    for (int j = 0; j < 4; j++) { float dl = v[j] - mean; sq += dl * dl; }
    float var = blockSum(sq, red) * (1.f / (D_ - 1));
    float inv = 1.f / (sqrtf(var) + EPS_);
    #pragma unroll
    for (int j = 0; j < 4; j++) {
        int i = t + j * 256;
        g_Cv[row + i] = to_tf32(gamma[i] * (v[j] - mean) * inv + beta[i]);
    }
}

// ---------------- launch ----------------
extern "C" void kernel_launch(void* const* d_in, const int* in_sizes, int n_in,
                              void* d_out, int out_size)
{
    const float* x     = (const float*)d_in[0];
    const float* Wq    = (const float*)d_in[1];
    const float* bq    = (const float*)d_in[2];
    const float* Wk    = (const float*)d_in[3];
    const float* Wv    = (const float*)d_in[4];
    const float* bv    = (const float*)d_in[5];
    const float* cw    = (const float*)d_in[6];
    const float* cb    = (const float*)d_in[7];
    const float* gamma = (const float*)d_in[8];
    const float* beta  = (const float*)d_in[9];
    const float* Wo    = (const float*)d_in[10];
    const float* bo    = (const float*)d_in[11];
    float* out = (float*)d_out;

    float *pXt, *pQKV, *pVt, *pC, *pA, *pS, *pWt, *pBias;
    cudaGetSymbolAddress((void**)&pXt,  g_Xt);
    cudaGetSymbolAddress((void**)&pQKV, g_QKV);
    cudaGetSymbolAddress((void**)&pVt,  g_Vt);
    cudaGetSymbolAddress((void**)&pC,   g_Cv);
    cudaGetSymbolAddress((void**)&pA,   g_Ao);
    cudaGetSymbolAddress((void**)&pS,   g_Sc);
    cudaGetSymbolAddress((void**)&pWt,  g_Wt);
    cudaGetSymbolAddress((void**)&pBias,g_bias);

    cudaFuncSetAttribute(mma_gemm<0,0>, cudaFuncAttributeMaxDynamicSharedMemorySize, SMEM_DYN);
    cudaFuncSetAttribute(mma_gemm<1,0>, cudaFuncAttributeMaxDynamicSharedMemorySize, SMEM_DYN);
    cudaFuncSetAttribute(mma_gemm<1,1>, cudaFuncAttributeMaxDynamicSharedMemorySize, SMEM_DYN);

    const int M = B_ * S_;
    const long long sSD = (long long)S_ * D_;
    const long long sSS = (long long)S_ * S_;
    const long long DD  = (long long)D_ * D_;

    float* pQ = pQKV;
    float* pK = pQKV + BSD;
    float* pV = pQKV + 2 * BSD;

    // launch 0: tf32-round x + pack bias
    const int n4 = (B_ * S_ * D_) / 4;
    convert_pack_kernel<<<n4 / 256 + 1, 256>>>(x, pXt, n4, bq, bv, pBias);

    // launches 1-4: transpose + round weights
    dim3 tb(256), tgW(D_ / 32, D_ / 32, 1);
    transpose_kernel<<<tgW, tb>>>(Wq, pWt + 0 * DD, D_, D_, 0, 0);
    transpose_kernel<<<tgW, tb>>>(Wk, pWt + 1 * DD, D_, D_, 0, 0);
    transpose_kernel<<<tgW, tb>>>(Wv, pWt + 2 * DD, D_, D_, 0, 0);
    transpose_kernel<<<tgW, tb>>>(Wo, pWt + 3 * DD, D_, D_, 0, 0);

    // launch 5 (ncu -s 5 -c 1 profiles THIS): fused QKV projection
    dim3 gblk(128);
    mma_gemm<1,1><<<dim3(3 * D_ / BN, M / BM, 1), gblk, SMEM_DYN>>>(
        pXt, pWt, pBias, nullptr, pQKV, M, 3 * D_, D_, 0, 0, 0, 1.f);

    // grouped conv + LN (uses exact x)
    conv_ln_kernel<<<dim3(S_ / 4, B_), dim3(256)>>>(x, cw, cb, gamma, beta);

    // V^T per batch (rounded)
    transpose_kernel<<<dim3(D_ / 32, S_ / 32, B_), tb>>>(pV, pVt, S_, D_, sSD, sSD);

    // scores = Q @ K^T * (1/32)
    mma_gemm<0,0><<<dim3(S_ / BN, S_ / BM, B_), gblk, SMEM_DYN>>>(
        pQ, pK, nullptr, nullptr, pS, S_, S_, D_, sSD, sSD, sSS, 0.03125f);

    // softmax rows (rounded probs)
    softmax_kernel<<<dim3(S_, B_), dim3(256)>>>();

    // attn_out = P @ Vt^T = P @ V
    mma_gemm<0,0><<<dim3(D_ / BN, S_ / BM, B_), gblk, SMEM_DYN>>>(
        pS, pVt, nullptr, nullptr, pA, S_, D_, S_, sSS, sSD, sSD, 1.f);

    // combined = LN(conv_ln + attn_out) (rounded)
    add_ln_kernel<<<dim3(S_, B_), dim3(256)>>>(gamma, beta);

    // out = combined @ Wo^T + bo + x (exact residual)
    mma_gemm<0,0><<<dim3(D_ / BN, M / BM, 1), gblk, SMEM_DYN>>>(
        pC, pWt + 3 * DD, bo, x, out, M, D_, D_, 0, 0, 0, 1.f);
}

// round 14
// speedup vs baseline: 1.7097x; 1.7097x over previous
#include <cuda_runtime.h>
#include <math.h>
#include <stdint.h>

#define B_ 4
#define S_ 2048
#define D_ 1024
#define GC_ 64
#define EPS_ 1e-6f

// GEMM tiling (R7-proven config)
#define BM 128
#define BN 128
#define BK 32
#define ST_ 3
#define ASTRIDE 36                        // 32 + 4 pad floats
#define STAGE_F (2 * 128 * ASTRIDE)       // floats per stage (A + B)
#define STAGE_BYTES (STAGE_F * 4)
#define SMEM_DYN (ST_ * STAGE_BYTES)

// conv_ln v2
#define CPOS 16
#define CONV_SMEM ((CPOS + 2) * D_ * 4 + 128)

#define BSD ((size_t)B_ * S_ * D_)

// ---------------- scratch (device globals: allocation-guard safe) ----------------
static __device__ __align__(256) float g_Xt [BSD];          // tf32-rounded x
static __device__ __align__(256) float g_QKV[3 * BSD];      // Q | K | V
static __device__ __align__(256) float g_Vt [BSD];
static __device__ __align__(256) float g_Cv [BSD];
static __device__ __align__(256) float g_Ao [BSD];
static __device__ __align__(256) float g_Sc [(size_t)B_*S_*S_];
static __device__ __align__(256) float g_Wt [(size_t)4*D_*D_];  // Wq^T|Wk^T|Wv^T|Wo^T
static __device__ __align__(256) float g_bias[3 * D_];

// ---------------- helpers ----------------
__device__ __forceinline__ uint32_t smem_u32(const void* p) {
    uint32_t a;
    asm("{ .reg .u64 t; cvta.to.shared.u64 t, %1; cvt.u32.u64 %0, t; }" : "=r"(a) : "l"(p));
    return a;
}
__device__ __forceinline__ float to_tf32(float x) {
    uint32_t o;
    asm("cvt.rna.tf32.f32 %0, %1;" : "=r"(o) : "f"(x));
    return __uint_as_float(o);
}
__device__ __forceinline__ void cpa16(uint32_t s, const float* g) {
    asm volatile("cp.async.cg.shared.global [%0], [%1], 16;" :: "r"(s), "l"(g));
}
#define CP_COMMIT() asm volatile("cp.async.commit_group;" ::: "memory")
#define CP_WAIT1()  asm volatile("cp.async.wait_group 1;"  ::: "memory")

__device__ __forceinline__ void ldsm4(uint32_t* r, uint32_t a) {
    asm volatile("ldmatrix.sync.aligned.m8n8.x4.shared.b16 {%0,%1,%2,%3}, [%4];"
        : "=r"(r[0]), "=r"(r[1]), "=r"(r[2]), "=r"(r[3]) : "r"(a));
}
__device__ __forceinline__ void mma_tf32(float* c, const uint32_t* a, const uint32_t* b) {
    asm volatile(
        "mma.sync.aligned.m16n8k8.row.col.f32.tf32.tf32.f32 "
        "{%0,%1,%2,%3}, {%4,%5,%6,%7}, {%8,%9}, {%0,%1,%2,%3};"
        : "+f"(c[0]), "+f"(c[1]), "+f"(c[2]), "+f"(c[3])
        : "r"(a[0]), "r"(a[1]), "r"(a[2]), "r"(a[3]), "r"(b[0]), "r"(b[1]));
}

// ---------------- mma.sync tf32 GEMM (exact R7 config) ----------------
// A [M,K] row-major, B [N,K] row-major (pre-rounded tf32).
// 128x128x32 tile, 256 threads, 8 warps (4m x 2n), warp tile 32x64.
// 3-stage cp.async ring, 2 CTAs/SM.
template <int CVT, int SPLIT>
__global__ void __launch_bounds__(256, 2) mma_gemm(
    const float* __restrict__ A, const float* __restrict__ B,
    const float* __restrict__ bias, const float* __restrict__ res,
    float* __restrict__ C, int M, int N, int Kd,
    long long sA, long long sB, long long sC, float alpha)
{
    extern __shared__ __align__(128) float smemf[];
    const uint32_t smem_base = smem_u32(smemf);

    const int t    = threadIdx.x;
    const int wid  = t >> 5;
    const int lane = t & 31;
    const int g    = lane >> 2;
    const int q    = lane & 3;
    const int wm   = wid & 3;
    const int wn   = wid >> 2;
    const int m0 = blockIdx.y * BM, n0 = blockIdx.x * BN;

    const float* Ab = A + (long long)blockIdx.z * sA;
    const float* Bb = B + (long long)blockIdx.z * sB;
    const float* Rb = res ? res + (long long)blockIdx.z * sC : nullptr;

    float acc[2][8][4];
    #pragma unroll
    for (int i = 0; i < 2; i++)
        #pragma unroll
        for (int j = 0; j < 8; j++)
            #pragma unroll
            for (int k = 0; k < 4; k++) acc[i][j][k] = 0.f;

    const int nk = Kd / BK;

    auto load_stage = [&](int j, int s) {
        const int k0 = j * BK;
        const uint32_t sb = smem_base + (uint32_t)s * STAGE_BYTES;
        #pragma unroll
        for (int i = 0; i < 4; i++) {
            int idx = t + i * 256;
            int row = idx >> 3, c4 = idx & 7;
            cpa16(sb + (uint32_t)(row * ASTRIDE + c4 * 4) * 4,
                  Ab + (long long)(m0 + row) * Kd + k0 + c4 * 4);
        }
        #pragma unroll
        for (int i = 0; i < 4; i++) {
            int idx = t + i * 256;
            int row = idx >> 3, c4 = idx & 7;
            cpa16(sb + (uint32_t)(128 * ASTRIDE + row * ASTRIDE + c4 * 4) * 4,
                  Bb + (long long)(n0 + row) * Kd + k0 + c4 * 4);
        }
    };

    load_stage(0, 0); CP_COMMIT();
    load_stage(1, 1); CP_COMMIT();

    const int arow = wm * 32;
    const int bcol = wn * 64;

    const int i8 = lane & 7, qd = lane >> 3;
    uint32_t offA[2], offB[4];
    #pragma unroll
    for (int mf = 0; mf < 2; mf++) {
        int row = arow + mf * 16 + i8 + (qd & 1) * 8;
        offA[mf] = (uint32_t)(row * ASTRIDE + (qd >> 1) * 4) * 4;
    }
    #pragma unroll
    for (int p = 0; p < 4; p++) {
        int row = bcol + p * 16 + i8 + (qd >> 1) * 8;
        offB[p] = (uint32_t)(row * ASTRIDE + (qd & 1) * 4) * 4;
    }

    int s = 0;
    for (int it = 0; it < nk; it++) {
        CP_WAIT1();
        __syncthreads();
        const int j = it + 2;
        if (j < nk) {
            int sn = s + 2; if (sn >= ST_) sn -= ST_;
            load_stage(j, sn);
        }
        CP_COMMIT();

        const uint32_t sAb = smem_base + (uint32_t)s * STAGE_BYTES;
        const uint32_t sBb = sAb + (uint32_t)(128 * ASTRIDE * 4);

        #pragma unroll
        for (int ks = 0; ks < 4; ks++) {
            const uint32_t kb = (uint32_t)(ks * 8 * 4);
            uint32_t a[2][4], b[8][2];
            #pragma unroll
            for (int mf = 0; mf < 2; mf++) ldsm4(a[mf], sAb + offA[mf] + kb);
            #pragma unroll
            for (int p = 0; p < 4; p++) ldsm4(&b[2 * p][0], sBb + offB[p] + kb);
            #pragma unroll
            for (int mf = 0; mf < 2; mf++)
                #pragma unroll
                for (int nf = 0; nf < 8; nf++)
                    mma_tf32(acc[mf][nf], a[mf], b[nf]);
        }
        __syncthreads();
        if (++s == ST_) s = 0;
    }

    // epilogue
    float* Cb;
    int colBase, rowStride;
    if (SPLIT) {
        Cb = C + (long long)(n0 >> 10) * (long long)(B_ * (size_t)S_ * D_);
        colBase = n0 & 1023;
        rowStride = 1024;
    } else {
        Cb = C + (long long)blockIdx.z * sC;
        colBase = n0;
        rowStride = N;
    }

    #pragma unroll
    for (int mf = 0; mf < 2; mf++) {
        #pragma unroll
        for (int nf = 0; nf < 8; nf++) {
            const int row  = m0 + arow + mf * 16 + g;
            const int colG = n0 + bcol + nf * 8 + q * 2;
            const int col  = colBase + bcol + nf * 8 + q * 2;
            float bx = 0.f, by = 0.f;
            if (bias) { bx = bias[colG]; by = bias[colG + 1]; }
            #pragma unroll
            for (int h = 0; h < 2; h++) {
                const int r = row + h * 8;
                float vx = acc[mf][nf][h * 2 + 0] * alpha + bx;
                float vy = acc[mf][nf][h * 2 + 1] * alpha + by;
                if (Rb) {
                    float2 rv = *(const float2*)&Rb[(long long)r * rowStride + col];
                    vx += rv.x; vy += rv.y;
                }
                if (CVT) { vx = to_tf32(vx); vy = to_tf32(vy); }
                float2 v; v.x = vx; v.y = vy;
                *(float2*)&Cb[(long long)r * rowStride + col] = v;
            }
        }
    }
}

// ---------------- convert x -> tf32 + pack bias ----------------
__global__ void __launch_bounds__(256) convert_pack_kernel(
    const float* __restrict__ in, float* __restrict__ out, int n4,
    const float* __restrict__ bq, const float* __restrict__ bv,
    float* __restrict__ biasOut)
{
    int i = blockIdx.x * 256 + threadIdx.x;
    if (blockIdx.x == gridDim.x - 1) {
        for (int k = threadIdx.x; k < 3 * D_; k += 256)
            biasOut[k] = (k < D_) ? bq[k] : ((k < 2 * D_) ? 0.f : bv[k - 2 * D_]);
        return;
    }
    if (i < n4) {
        float4 v = ((const float4*)in)[i];
        v.x = to_tf32(v.x); v.y = to_tf32(v.y);
        v.z = to_tf32(v.z); v.w = to_tf32(v.w);
        ((float4*)out)[i] = v;
    }
}

// ---------------- batched weight transpose (4 matrices in one launch) ----------------
__global__ void __launch_bounds__(256) transpose_w4_kernel(
    const float* __restrict__ w0, const float* __restrict__ w1,
    const float* __restrict__ w2, const float* __restrict__ w3,
    float* __restrict__ outBase)
{
    __shared__ float tile[32][33];
    const float* in = (blockIdx.z == 0) ? w0 : (blockIdx.z == 1) ? w1 :
                      (blockIdx.z == 2) ? w2 : w3;
    float* out = outBase + (size_t)blockIdx.z * D_ * D_;
    const int tx = threadIdx.x & 31, ty = threadIdx.x >> 5;
    const int c0 = blockIdx.x * 32, r0 = blockIdx.y * 32;
    #pragma unroll
    for (int j = 0; j < 4; j++)
        tile[ty + j * 8][tx] = in[(long long)(r0 + ty + j * 8) * D_ + c0 + tx];
    __syncthreads();
    #pragma unroll
    for (int j = 0; j < 4; j++)
        out[(long long)(c0 + ty + j * 8) * D_ + r0 + tx] = to_tf32(tile[tx][ty + j * 8]);
}

// ---------------- batched V transpose ----------------
__global__ void __launch_bounds__(256) transpose_kernel(
    const float* __restrict__ in, float* __restrict__ out,
    int R, int C, long long sIn, long long sOut)
{
    __shared__ float tile[32][33];
    in  += (long long)blockIdx.z * sIn;
    out += (long long)blockIdx.z * sOut;
    const int tx = threadIdx.x & 31, ty = threadIdx.x >> 5;
    const int c0 = blockIdx.x * 32, r0 = blockIdx.y * 32;
    #pragma unroll
    for (int j = 0; j < 4; j++)
        tile[ty + j * 8][tx] = in[(long long)(r0 + ty + j * 8) * C + c0 + tx];
    __syncthreads();
    #pragma unroll
    for (int j = 0; j < 4; j++)
        out[(long long)(c0 + ty + j * 8) * R + r0 + tx] = to_tf32(tile[tx][ty + j * 8]);
}

// ---------------- reductions ----------------
__device__ __forceinline__ float warpSum(float v) {
    #pragma unroll
    for (int o = 16; o > 0; o >>= 1) v += __shfl_xor_sync(0xffffffffu, v, o);
    return v;
}
__device__ __forceinline__ float warpMax(float v) {
    #pragma unroll
    for (int o = 16; o > 0; o >>= 1) v = fmaxf(v, __shfl_xor_sync(0xffffffffu, v, o));
    return v;
}
__device__ __forceinline__ float blockSum(float v, float* red) {
    int t = threadIdx.x, lane = t & 31, w = t >> 5;
    v = warpSum(v);
    if (lane == 0) red[w] = v;
    __syncthreads();
    if (w == 0) {
        float x = (lane < 8) ? red[lane] : 0.f;
        x = warpSum(x);
        if (lane == 0) red[0] = x;
    }
    __syncthreads();
    float r = red[0];
    __syncthreads();
    return r;
}
__device__ __forceinline__ float blockMax(float v, float* red) {
    int t = threadIdx.x, lane = t & 31, w = t >> 5;
    v = warpMax(v);
    if (lane == 0) red[w] = v;
    __syncthreads();
    if (w == 0) {
        float x = (lane < 8) ? red[lane] : -1e30f;
        x = warpMax(x);
        if (lane == 0) red[0] = x;
    }
    __syncthreads();
    float r = red[0];
    __syncthreads();
    return r;
}

// ---------------- grouped conv1d (K=3, pad=1) + LayerNorm, 16 pos/block --------
__global__ void __launch_bounds__(256) conv_ln_kernel(
    const float* __restrict__ x, const float* __restrict__ cw,
    const float* __restrict__ cb, const float* __restrict__ gamma,
    const float* __restrict__ beta)
{
    extern __shared__ float cs[];               // xs[(CPOS+2)][D_] then red[32]
    float (*xs)[D_] = (float(*)[D_])cs;
    float* red = cs + (CPOS + 2) * D_;

    const int t  = threadIdx.x;
    const int s0 = blockIdx.x * CPOS;
    const int b  = blockIdx.y;
    const float* xb = x + (size_t)b * S_ * D_;

    // load CPOS+2 rows (s0-1 .. s0+CPOS), one float4 per thread per row
    #pragma unroll
    for (int r = 0; r < CPOS + 2; r++) {
        int sr = s0 - 1 + r;
        float4 v;
        if (sr >= 0 && sr < S_) v = ((const float4*)(xb + (size_t)sr * D_))[t];
        else                    v = make_float4(0.f, 0.f, 0.f, 0.f);
        ((float4*)xs[r])[t] = v;
    }
    __syncthreads();

    const int d0 = t * 4;
    const int gb = (d0 >> 6) << 6;              // same group for all 4 channels

    float acc[4][CPOS];
    #pragma unroll
    for (int dd = 0; dd < 4; dd++) {
        float bias0 = cb[d0 + dd];
        #pragma unroll
        for (int p = 0; p < CPOS; p++) acc[dd][p] = bias0;
    }

    for (int c = 0; c < GC_; c++) {
        float xv[CPOS + 2];
        #pragma unroll
        for (int r = 0; r < CPOS + 2; r++) xv[r] = xs[r][gb + c];
        #pragma unroll
        for (int dd = 0; dd < 4; dd++) {
            const float* wp = cw + (size_t)(d0 + dd) * GC_ * 3 + c * 3;
            float w0 = wp[0], w1 = wp[1], w2 = wp[2];
            #pragma unroll
            for (int p = 0; p < CPOS; p++)
                acc[dd][p] += w0 * xv[p] + w1 * xv[p + 1] + w2 * xv[p + 2];
        }
    }

    const float4 gv  = *(const float4*)&gamma[d0];
    const float4 bvv = *(const float4*)&beta[d0];
    const float gvl[4] = {gv.x, gv.y, gv.z, gv.w};
    const float bvl[4] = {bvv.x, bvv.y, bvv.z, bvv.w};

    for (int p = 0; p < CPOS; p++) {
        float s = acc[0][p] + acc[1][p] + acc[2][p] + acc[3][p];
        float mean = blockSum(s, red) * (1.f / D_);
        float sq = 0.f;
        #pragma unroll
        for (int dd = 0; dd < 4; dd++) { float dl = acc[dd][p] - mean; sq += dl * dl; }
        float var = blockSum(sq, red) * (1.f / (D_ - 1));
        float inv = 1.f / (sqrtf(var) + EPS_);
        float* out = g_Cv + ((size_t)b * S_ + s0 + p) * D_;
        float4 ov;
        ov.x = gvl[0] * (acc[0][p] - mean) * inv + bvl[0];
        ov.y = gvl[1] * (acc[1][p] - mean) * inv + bvl[1];
        ov.z = gvl[2] * (acc[2][p] - mean) * inv + bvl[2];
        ov.w = gvl[3] * (acc[3][p] - mean) * inv + bvl[3];
        *(float4*)&out[d0] = ov;
    }
}

// ---------------- row softmax (writes tf32-rounded probs) ----------------
__global__ void __launch_bounds__(256) softmax_kernel()
{
    __shared__ float red[32];
    const int t = threadIdx.x;
    float* row = g_Sc + ((size_t)blockIdx.y * S_ + blockIdx.x) * S_;

    float v[8];
    float m = -1e30f;
    #pragma unroll
    for (int j = 0; j < 8; j++) { v[j] = row[t + j * 256]; m = fmaxf(m, v[j]); }
    m = blockMax(m, red);

    float sum = 0.f;
    #pragma unroll
    for (int j = 0; j < 8; j++) { v[j] = __expf(v[j] - m); sum += v[j]; }
    sum = blockSum(sum, red);
    float inv = 1.f / sum;
    #pragma unroll
    for (int j = 0; j < 8; j++) row[t + j * 256] = to_tf32(v[j] * inv);
}

// ---------------- combined = LN(conv_ln + attn_out) -> g_Cv (tf32-rounded) ------
__global__ void __launch_bounds__(256) add_ln_kernel(
    const float* __restrict__ gamma, const float* __restrict__ beta)
{
    __shared__ float red[32];
    const int t = threadIdx.x;
    const size_t row = ((size_t)blockIdx.y * S_ + blockIdx.x) * D_;

    float v[4];
    float s = 0.f;
    #pragma unroll
    for (int j = 0; j < 4; j++) {
        int i = t + j * 256;
        v[j] = g_Cv[row + i] + g_Ao[row + i];
        s += v[j];
    }
    float mean = blockSum(s, red) * (1.f / D_);
    float sq = 0.f;
    #pragma unroll
    for (int j = 0; j < 4; j++) { float dl = v[j] - mean; sq += dl * dl; }
    float var = blockSum(sq, red) * (1.f / (D_ - 1));
    float inv = 1.f / (sqrtf(var) + EPS_);
    #pragma unroll
    for (int j = 0; j < 4; j++) {
        int i = t + j * 256;
        g_Cv[row + i] = to_tf32(gamma[i] * (v[j] - mean) * inv + beta[i]);
    }
}

// ---------------- launch ----------------
extern "C" void kernel_launch(void* const* d_in, const int* in_sizes, int n_in,
                              void* d_out, int out_size)
{
    const float* x     = (const float*)d_in[0];
    const float* Wq    = (const float*)d_in[1];
    const float* bq    = (const float*)d_in[2];
    const float* Wk    = (const float*)d_in[3];
    const float* Wv    = (const float*)d_in[4];
    const float* bv    = (const float*)d_in[5];
    const float* cw    = (const float*)d_in[6];
    const float* cb    = (const float*)d_in[7];
    const float* gamma = (const float*)d_in[8];
    const float* beta  = (const float*)d_in[9];
    const float* Wo    = (const float*)d_in[10];
    const float* bo    = (const float*)d_in[11];
    float* out = (float*)d_out;

    float *pXt, *pQKV, *pVt, *pC, *pA, *pS, *pWt, *pBias;
    cudaGetSymbolAddress((void**)&pXt,  g_Xt);
    cudaGetSymbolAddress((void**)&pQKV, g_QKV);
    cudaGetSymbolAddress((void**)&pVt,  g_Vt);
    cudaGetSymbolAddress((void**)&pC,   g_Cv);
    cudaGetSymbolAddress((void**)&pA,   g_Ao);
    cudaGetSymbolAddress((void**)&pS,   g_Sc);
    cudaGetSymbolAddress((void**)&pWt,  g_Wt);
    cudaGetSymbolAddress((void**)&pBias,g_bias);

    cudaFuncSetAttribute(mma_gemm<0,0>, cudaFuncAttributeMaxDynamicSharedMemorySize, SMEM_DYN);
    cudaFuncSetAttribute(mma_gemm<1,0>, cudaFuncAttributeMaxDynamicSharedMemorySize, SMEM_DYN);
    cudaFuncSetAttribute(mma_gemm<1,1>, cudaFuncAttributeMaxDynamicSharedMemorySize, SMEM_DYN);
    cudaFuncSetAttribute(conv_ln_kernel, cudaFuncAttributeMaxDynamicSharedMemorySize, CONV_SMEM);

    const int M = B_ * S_;
    const long long sSD = (long long)S_ * D_;
    const long long sSS = (long long)S_ * S_;
    const long long DD  = (long long)D_ * D_;

    float* pQ = pQKV;
    float* pK = pQKV + BSD;
    float* pV = pQKV + 2 * BSD;

    // tf32-round x + pack bias
    const int n4 = (B_ * S_ * D_) / 4;
    convert_pack_kernel<<<n4 / 256 + 1, 256>>>(x, pXt, n4, bq, bv, pBias);

    // batched weight transpose+round (one launch)
    dim3 tb(256);
    transpose_w4_kernel<<<dim3(D_ / 32, D_ / 32, 4), tb>>>(Wq, Wk, Wv, Wo, pWt);

    // fused QKV projection
    dim3 gblk(256);
    mma_gemm<1,1><<<dim3(3 * D_ / BN, M / BM, 1), gblk, SMEM_DYN>>>(
        pXt, pWt, pBias, nullptr, pQKV, M, 3 * D_, D_, 0, 0, 0, 1.f);

    // grouped conv + LN (16 positions/block)
    conv_ln_kernel<<<dim3(S_ / CPOS, B_), dim3(256), CONV_SMEM>>>(x, cw, cb, gamma, beta);

    // V^T per batch (rounded)
    transpose_kernel<<<dim3(D_ / 32, S_ / 32, B_), tb>>>(pV, pVt, S_, D_, sSD, sSD);

    // scores = Q @ K^T * (1/32)
    mma_gemm<0,0><<<dim3(S_ / BN, S_ / BM, B_), gblk, SMEM_DYN>>>(
        pQ, pK, nullptr, nullptr, pS, S_, S_, D_, sSD, sSD, sSS, 0.03125f);

    // softmax rows (rounded probs)
    softmax_kernel<<<dim3(S_, B_), dim3(256)>>>();

    // attn_out = P @ Vt^T = P @ V
    mma_gemm<0,0><<<dim3(D_ / BN, S_ / BM, B_), gblk, SMEM_DYN>>>(
        pS, pVt, nullptr, nullptr, pA, S_, D_, S_, sSS, sSD, sSD, 1.f);

    // combined = LN(conv_ln + attn_out) (rounded)
    add_ln_kernel<<<dim3(S_, B_), dim3(256)>>>(gamma, beta);

    // out = combined @ Wo^T + bo + x (exact residual)
    mma_gemm<0,0><<<dim3(D_ / BN, M / BM, 1), gblk, SMEM_DYN>>>(
        pC, pWt + 3 * DD, bo, x, out, M, D_, D_, 0, 0, 0, 1.f);
}

// round 15
// speedup vs baseline: 1.8306x; 1.0707x over previous
#include <cuda_runtime.h>
#include <math.h>
#include <stdint.h>

#define B_ 4
#define S_ 2048
#define D_ 1024
#define GC_ 64
#define EPS_ 1e-6f

// GEMM tiling (R7-proven config)
#define BM 128
#define BN 128
#define BK 32
#define ST_ 3
#define ASTRIDE 36                        // 32 + 4 pad floats
#define STAGE_F (2 * 128 * ASTRIDE)       // floats per stage (A + B)
#define STAGE_BYTES (STAGE_F * 4)
#define SMEM_DYN (ST_ * STAGE_BYTES)

// conv_ln v3
#define CPOS 8
#define CONV_SMEM ((CPOS + 2) * D_ * 4 + 128)

#define BSD ((size_t)B_ * S_ * D_)

// ---------------- scratch (device globals: allocation-guard safe) ----------------
static __device__ __align__(256) float g_Xt [BSD];          // tf32-rounded x
static __device__ __align__(256) float g_QKV[3 * BSD];      // Q | K | V
static __device__ __align__(256) float g_Vt [BSD];
static __device__ __align__(256) float g_Cv [BSD];
static __device__ __align__(256) float g_Ao [BSD];
static __device__ __align__(256) float g_Sc [(size_t)B_*S_*S_];
static __device__ __align__(256) float g_Wt [(size_t)4*D_*D_];  // Wq^T|Wk^T|Wv^T|Wo^T
static __device__ __align__(256) float g_bias[3 * D_];

// ---------------- helpers ----------------
__device__ __forceinline__ uint32_t smem_u32(const void* p) {
    uint32_t a;
    asm("{ .reg .u64 t; cvta.to.shared.u64 t, %1; cvt.u32.u64 %0, t; }" : "=r"(a) : "l"(p));
    return a;
}
__device__ __forceinline__ float to_tf32(float x) {
    uint32_t o;
    asm("cvt.rna.tf32.f32 %0, %1;" : "=r"(o) : "f"(x));
    return __uint_as_float(o);
}
__device__ __forceinline__ void cpa16(uint32_t s, const float* g) {
    asm volatile("cp.async.cg.shared.global [%0], [%1], 16;" :: "r"(s), "l"(g));
}
#define CP_COMMIT() asm volatile("cp.async.commit_group;" ::: "memory")
#define CP_WAIT1()  asm volatile("cp.async.wait_group 1;"  ::: "memory")

__device__ __forceinline__ void ldsm4(uint32_t* r, uint32_t a) {
    asm volatile("ldmatrix.sync.aligned.m8n8.x4.shared.b16 {%0,%1,%2,%3}, [%4];"
        : "=r"(r[0]), "=r"(r[1]), "=r"(r[2]), "=r"(r[3]) : "r"(a));
}
__device__ __forceinline__ void mma_tf32(float* c, const uint32_t* a, const uint32_t* b) {
    asm volatile(
        "mma.sync.aligned.m16n8k8.row.col.f32.tf32.tf32.f32 "
        "{%0,%1,%2,%3}, {%4,%5,%6,%7}, {%8,%9}, {%0,%1,%2,%3};"
        : "+f"(c[0]), "+f"(c[1]), "+f"(c[2]), "+f"(c[3])
        : "r"(a[0]), "r"(a[1]), "r"(a[2]), "r"(a[3]), "r"(b[0]), "r"(b[1]));
}

// ---------------- mma.sync tf32 GEMM (exact R7 config) ----------------
template <int CVT, int SPLIT>
__global__ void __launch_bounds__(256, 2) mma_gemm(
    const float* __restrict__ A, const float* __restrict__ B,
    const float* __restrict__ bias, const float* __restrict__ res,
    float* __restrict__ C, int M, int N, int Kd,
    long long sA, long long sB, long long sC, float alpha)
{
    extern __shared__ __align__(128) float smemf[];
    const uint32_t smem_base = smem_u32(smemf);

    const int t    = threadIdx.x;
    const int wid  = t >> 5;
    const int lane = t & 31;
    const int g    = lane >> 2;
    const int q    = lane & 3;
    const int wm   = wid & 3;
    const int wn   = wid >> 2;
    const int m0 = blockIdx.y * BM, n0 = blockIdx.x * BN;

    const float* Ab = A + (long long)blockIdx.z * sA;
    const float* Bb = B + (long long)blockIdx.z * sB;
    const float* Rb = res ? res + (long long)blockIdx.z * sC : nullptr;

    float acc[2][8][4];
    #pragma unroll
    for (int i = 0; i < 2; i++)
        #pragma unroll
        for (int j = 0; j < 8; j++)
            #pragma unroll
            for (int k = 0; k < 4; k++) acc[i][j][k] = 0.f;

    const int nk = Kd / BK;

    auto load_stage = [&](int j, int s) {
        const int k0 = j * BK;
        const uint32_t sb = smem_base + (uint32_t)s * STAGE_BYTES;
        #pragma unroll
        for (int i = 0; i < 4; i++) {
            int idx = t + i * 256;
            int row = idx >> 3, c4 = idx & 7;
            cpa16(sb + (uint32_t)(row * ASTRIDE + c4 * 4) * 4,
                  Ab + (long long)(m0 + row) * Kd + k0 + c4 * 4);
        }
        #pragma unroll
        for (int i = 0; i < 4; i++) {
            int idx = t + i * 256;
            int row = idx >> 3, c4 = idx & 7;
            cpa16(sb + (uint32_t)(128 * ASTRIDE + row * ASTRIDE + c4 * 4) * 4,
                  Bb + (long long)(n0 + row) * Kd + k0 + c4 * 4);
        }
    };

    load_stage(0, 0); CP_COMMIT();
    load_stage(1, 1); CP_COMMIT();

    const int arow = wm * 32;
    const int bcol = wn * 64;

    const int i8 = lane & 7, qd = lane >> 3;
    uint32_t offA[2], offB[4];
    #pragma unroll
    for (int mf = 0; mf < 2; mf++) {
        int row = arow + mf * 16 + i8 + (qd & 1) * 8;
        offA[mf] = (uint32_t)(row * ASTRIDE + (qd >> 1) * 4) * 4;
    }
    #pragma unroll
    for (int p = 0; p < 4; p++) {
        int row = bcol + p * 16 + i8 + (qd >> 1) * 8;
        offB[p] = (uint32_t)(row * ASTRIDE + (qd & 1) * 4) * 4;
    }

    int s = 0;
    for (int it = 0; it < nk; it++) {
        CP_WAIT1();
        __syncthreads();
        const int j = it + 2;
        if (j < nk) {
            int sn = s + 2; if (sn >= ST_) sn -= ST_;
            load_stage(j, sn);
        }
        CP_COMMIT();

        const uint32_t sAb = smem_base + (uint32_t)s * STAGE_BYTES;
        const uint32_t sBb = sAb + (uint32_t)(128 * ASTRIDE * 4);

        #pragma unroll
        for (int ks = 0; ks < 4; ks++) {
            const uint32_t kb = (uint32_t)(ks * 8 * 4);
            uint32_t a[2][4], b[8][2];
            #pragma unroll
            for (int mf = 0; mf < 2; mf++) ldsm4(a[mf], sAb + offA[mf] + kb);
            #pragma unroll
            for (int p = 0; p < 4; p++) ldsm4(&b[2 * p][0], sBb + offB[p] + kb);
            #pragma unroll
            for (int mf = 0; mf < 2; mf++)
                #pragma unroll
                for (int nf = 0; nf < 8; nf++)
                    mma_tf32(acc[mf][nf], a[mf], b[nf]);
        }
        __syncthreads();
        if (++s == ST_) s = 0;
    }

    // epilogue
    float* Cb;
    int colBase, rowStride;
    if (SPLIT) {
        Cb = C + (long long)(n0 >> 10) * (long long)(B_ * (size_t)S_ * D_);
        colBase = n0 & 1023;
        rowStride = 1024;
    } else {
        Cb = C + (long long)blockIdx.z * sC;
        colBase = n0;
        rowStride = N;
    }

    #pragma unroll
    for (int mf = 0; mf < 2; mf++) {
        #pragma unroll
        for (int nf = 0; nf < 8; nf++) {
            const int row  = m0 + arow + mf * 16 + g;
            const int colG = n0 + bcol + nf * 8 + q * 2;
            const int col  = colBase + bcol + nf * 8 + q * 2;
            float bx = 0.f, by = 0.f;
            if (bias) { bx = bias[colG]; by = bias[colG + 1]; }
            #pragma unroll
            for (int h = 0; h < 2; h++) {
                const int r = row + h * 8;
                float vx = acc[mf][nf][h * 2 + 0] * alpha + bx;
                float vy = acc[mf][nf][h * 2 + 1] * alpha + by;
                if (Rb) {
                    float2 rv = *(const float2*)&Rb[(long long)r * rowStride + col];
                    vx += rv.x; vy += rv.y;
                }
                if (CVT) { vx = to_tf32(vx); vy = to_tf32(vy); }
                float2 v; v.x = vx; v.y = vy;
                *(float2*)&Cb[(long long)r * rowStride + col] = v;
            }
        }
    }
}

// ---------------- convert x -> tf32 + pack bias ----------------
__global__ void __launch_bounds__(256) convert_pack_kernel(
    const float* __restrict__ in, float* __restrict__ out, int n4,
    const float* __restrict__ bq, const float* __restrict__ bv,
    float* __restrict__ biasOut)
{
    int i = blockIdx.x * 256 + threadIdx.x;
    if (blockIdx.x == gridDim.x - 1) {
        for (int k = threadIdx.x; k < 3 * D_; k += 256)
            biasOut[k] = (k < D_) ? bq[k] : ((k < 2 * D_) ? 0.f : bv[k - 2 * D_]);
        return;
    }
    if (i < n4) {
        float4 v = ((const float4*)in)[i];
        v.x = to_tf32(v.x); v.y = to_tf32(v.y);
        v.z = to_tf32(v.z); v.w = to_tf32(v.w);
        ((float4*)out)[i] = v;
    }
}

// ---------------- batched weight transpose (4 matrices, one launch) ----------------
__global__ void __launch_bounds__(256) transpose_w4_kernel(
    const float* __restrict__ w0, const float* __restrict__ w1,
    const float* __restrict__ w2, const float* __restrict__ w3,
    float* __restrict__ outBase)
{
    __shared__ float tile[32][33];
    const float* in = (blockIdx.z == 0) ? w0 : (blockIdx.z == 1) ? w1 :
                      (blockIdx.z == 2) ? w2 : w3;
    float* out = outBase + (size_t)blockIdx.z * D_ * D_;
    const int tx = threadIdx.x & 31, ty = threadIdx.x >> 5;
    const int c0 = blockIdx.x * 32, r0 = blockIdx.y * 32;
    #pragma unroll
    for (int j = 0; j < 4; j++)
        tile[ty + j * 8][tx] = in[(long long)(r0 + ty + j * 8) * D_ + c0 + tx];
    __syncthreads();
    #pragma unroll
    for (int j = 0; j < 4; j++)
        out[(long long)(c0 + ty + j * 8) * D_ + r0 + tx] = to_tf32(tile[tx][ty + j * 8]);
}

// ---------------- batched V transpose ----------------
__global__ void __launch_bounds__(256) transpose_kernel(
    const float* __restrict__ in, float* __restrict__ out,
    int R, int C, long long sIn, long long sOut)
{
    __shared__ float tile[32][33];
    in  += (long long)blockIdx.z * sIn;
    out += (long long)blockIdx.z * sOut;
    const int tx = threadIdx.x & 31, ty = threadIdx.x >> 5;
    const int c0 = blockIdx.x * 32, r0 = blockIdx.y * 32;
    #pragma unroll
    for (int j = 0; j < 4; j++)
        tile[ty + j * 8][tx] = in[(long long)(r0 + ty + j * 8) * C + c0 + tx];
    __syncthreads();
    #pragma unroll
    for (int j = 0; j < 4; j++)
        out[(long long)(c0 + ty + j * 8) * R + r0 + tx] = to_tf32(tile[tx][ty + j * 8]);
}

// ---------------- reductions ----------------
__device__ __forceinline__ float warpSum(float v) {
    #pragma unroll
    for (int o = 16; o > 0; o >>= 1) v += __shfl_xor_sync(0xffffffffu, v, o);
    return v;
}
__device__ __forceinline__ float warpMax(float v) {
    #pragma unroll
    for (int o = 16; o > 0; o >>= 1) v = fmaxf(v, __shfl_xor_sync(0xffffffffu, v, o));
    return v;
}
__device__ __forceinline__ float blockSum(float v, float* red) {
    int t = threadIdx.x, lane = t & 31, w = t >> 5;
    v = warpSum(v);
    if (lane == 0) red[w] = v;
    __syncthreads();
    if (w == 0) {
        float x = (lane < 8) ? red[lane] : 0.f;
        x = warpSum(x);
        if (lane == 0) red[0] = x;
    }
    __syncthreads();
    float r = red[0];
    __syncthreads();
    return r;
}
__device__ __forceinline__ float blockMax(float v, float* red) {
    int t = threadIdx.x, lane = t & 31, w = t >> 5;
    v = warpMax(v);
    if (lane == 0) red[w] = v;
    __syncthreads();
    if (w == 0) {
        float x = (lane < 8) ? red[lane] : -1e30f;
        x = warpMax(x);
        if (lane == 0) red[0] = x;
    }
    __syncthreads();
    float r = red[0];
    __syncthreads();
    return r;
}

// ---------------- grouped conv1d (K=3, pad=1) + LayerNorm, v3 ----------------
// CPOS=8 positions/block, c-loop stepped by 2 with float2 smem/weight loads,
// 3 CTAs/SM target.
__global__ void __launch_bounds__(256, 3) conv_ln_kernel(
    const float* __restrict__ x, const float* __restrict__ cw,
    const float* __restrict__ cb, const float* __restrict__ gamma,
    const float* __restrict__ beta)
{
    extern __shared__ float cs[];               // xs[(CPOS+2)][D_] then red[32]
    float (*xs)[D_] = (float(*)[D_])cs;
    float* red = cs + (CPOS + 2) * D_;

    const int t  = threadIdx.x;
    const int s0 = blockIdx.x * CPOS;
    const int b  = blockIdx.y;
    const float* xb = x + (size_t)b * S_ * D_;

    // load CPOS+2 rows (s0-1 .. s0+CPOS), one float4 per thread per row
    #pragma unroll
    for (int r = 0; r < CPOS + 2; r++) {
        int sr = s0 - 1 + r;
        float4 v;
        if (sr >= 0 && sr < S_) v = ((const float4*)(xb + (size_t)sr * D_))[t];
        else                    v = make_float4(0.f, 0.f, 0.f, 0.f);
        ((float4*)xs[r])[t] = v;
    }
    __syncthreads();

    const int d0 = t * 4;
    const int gb = (d0 >> 6) << 6;              // group base channel

    float acc[4][CPOS];
    #pragma unroll
    for (int dd = 0; dd < 4; dd++) {
        float bias0 = cb[d0 + dd];
        #pragma unroll
        for (int p = 0; p < CPOS; p++) acc[dd][p] = bias0;
    }

    for (int c = 0; c < GC_; c += 2) {
        float2 xv[CPOS + 2];
        #pragma unroll
        for (int r = 0; r < CPOS + 2; r++)
            xv[r] = *(const float2*)&xs[r][gb + c];
        #pragma unroll
        for (int dd = 0; dd < 4; dd++) {
            const float* wp = cw + (size_t)(d0 + dd) * (GC_ * 3) + c * 3;
            float2 wA = *(const float2*)&wp[0];   // w0a, w1a
            float2 wB = *(const float2*)&wp[2];   // w2a, w0b
            float2 wC = *(const float2*)&wp[4];   // w1b, w2b
            #pragma unroll
            for (int p = 0; p < CPOS; p++)
                acc[dd][p] += wA.x * xv[p].x + wA.y * xv[p + 1].x + wB.x * xv[p + 2].x
                            + wB.y * xv[p].y + wC.x * xv[p + 1].y + wC.y * xv[p + 2].y;
        }
    }

    const float4 gv  = *(const float4*)&gamma[d0];
    const float4 bvv = *(const float4*)&beta[d0];
    const float gvl[4] = {gv.x, gv.y, gv.z, gv.w};
    const float bvl[4] = {bvv.x, bvv.y, bvv.z, bvv.w};

    for (int p = 0; p < CPOS; p++) {
        float s = acc[0][p] + acc[1][p] + acc[2][p] + acc[3][p];
        float mean = blockSum(s, red) * (1.f / D_);
        float sq = 0.f;
        #pragma unroll
        for (int dd = 0; dd < 4; dd++) { float dl = acc[dd][p] - mean; sq += dl * dl; }
        float var = blockSum(sq, red) * (1.f / (D_ - 1));
        float inv = 1.f / (sqrtf(var) + EPS_);
        float* out = g_Cv + ((size_t)b * S_ + s0 + p) * D_;
        float4 ov;
        ov.x = gvl[0] * (acc[0][p] - mean) * inv + bvl[0];
        ov.y = gvl[1] * (acc[1][p] - mean) * inv + bvl[1];
        ov.z = gvl[2] * (acc[2][p] - mean) * inv + bvl[2];
        ov.w = gvl[3] * (acc[3][p] - mean) * inv + bvl[3];
        *(float4*)&out[d0] = ov;
    }
}

// ---------------- row softmax (writes tf32-rounded probs) ----------------
__global__ void __launch_bounds__(256) softmax_kernel()
{
    __shared__ float red[32];
    const int t = threadIdx.x;
    float* row = g_Sc + ((size_t)blockIdx.y * S_ + blockIdx.x) * S_;

    float v[8];
    float m = -1e30f;
    #pragma unroll
    for (int j = 0; j < 8; j++) { v[j] = row[t + j * 256]; m = fmaxf(m, v[j]); }
    m = blockMax(m, red);

    float sum = 0.f;
    #pragma unroll
    for (int j = 0; j < 8; j++) { v[j] = __expf(v[j] - m); sum += v[j]; }
    sum = blockSum(sum, red);
    float inv = 1.f / sum;
    #pragma unroll
    for (int j = 0; j < 8; j++) row[t + j * 256] = to_tf32(v[j] * inv);
}

// ---------------- combined = LN(conv_ln + attn_out) -> g_Cv (tf32-rounded) ------
__global__ void __launch_bounds__(256) add_ln_kernel(
    const float* __restrict__ gamma, const float* __restrict__ beta)
{
    __shared__ float red[32];
    const int t = threadIdx.x;
    const size_t row = ((size_t)blockIdx.y * S_ + blockIdx.x) * D_;

    float v[4];
    float s = 0.f;
    #pragma unroll
    for (int j = 0; j < 4; j++) {
        int i = t + j * 256;
        v[j] = g_Cv[row + i] + g_Ao[row + i];
        s += v[j];
    }
    float mean = blockSum(s, red) * (1.f / D_);
    float sq = 0.f;
    #pragma unroll
    for (int j = 0; j < 4; j++) { float dl = v[j] - mean; sq += dl * dl; }
    float var = blockSum(sq, red) * (1.f / (D_ - 1));
    float inv = 1.f / (sqrtf(var) + EPS_);
    #pragma unroll
    for (int j = 0; j < 4; j++) {
        int i = t + j * 256;
        g_Cv[row + i] = to_tf32(gamma[i] * (v[j] - mean) * inv + beta[i]);
    }
}

// ---------------- launch ----------------
extern "C" void kernel_launch(void* const* d_in, const int* in_sizes, int n_in,
                              void* d_out, int out_size)
{
    const float* x     = (const float*)d_in[0];
    const float* Wq    = (const float*)d_in[1];
    const float* bq    = (const float*)d_in[2];
    const float* Wk    = (const float*)d_in[3];
    const float* Wv    = (const float*)d_in[4];
    const float* bv    = (const float*)d_in[5];
    const float* cw    = (const float*)d_in[6];
    const float* cb    = (const float*)d_in[7];
    const float* gamma = (const float*)d_in[8];
    const float* beta  = (const float*)d_in[9];
    const float* Wo    = (const float*)d_in[10];
    const float* bo    = (const float*)d_in[11];
    float* out = (float*)d_out;

    float *pXt, *pQKV, *pVt, *pC, *pA, *pS, *pWt, *pBias;
    cudaGetSymbolAddress((void**)&pXt,  g_Xt);
    cudaGetSymbolAddress((void**)&pQKV, g_QKV);
    cudaGetSymbolAddress((void**)&pVt,  g_Vt);
    cudaGetSymbolAddress((void**)&pC,   g_Cv);
    cudaGetSymbolAddress((void**)&pA,   g_Ao);
    cudaGetSymbolAddress((void**)&pS,   g_Sc);
    cudaGetSymbolAddress((void**)&pWt,  g_Wt);
    cudaGetSymbolAddress((void**)&pBias,g_bias);

    cudaFuncSetAttribute(mma_gemm<0,0>, cudaFuncAttributeMaxDynamicSharedMemorySize, SMEM_DYN);
    cudaFuncSetAttribute(mma_gemm<1,0>, cudaFuncAttributeMaxDynamicSharedMemorySize, SMEM_DYN);
    cudaFuncSetAttribute(mma_gemm<1,1>, cudaFuncAttributeMaxDynamicSharedMemorySize, SMEM_DYN);
    cudaFuncSetAttribute(conv_ln_kernel, cudaFuncAttributeMaxDynamicSharedMemorySize, CONV_SMEM);

    const int M = B_ * S_;
    const long long sSD = (long long)S_ * D_;
    const long long sSS = (long long)S_ * S_;
    const long long DD  = (long long)D_ * D_;

    float* pQ = pQKV;
    float* pK = pQKV + BSD;
    float* pV = pQKV + 2 * BSD;

    // tf32-round x + pack bias
    const int n4 = (B_ * S_ * D_) / 4;
    convert_pack_kernel<<<n4 / 256 + 1, 256>>>(x, pXt, n4, bq, bv, pBias);

    // batched weight transpose+round (one launch)
    dim3 tb(256);
    transpose_w4_kernel<<<dim3(D_ / 32, D_ / 32, 4), tb>>>(Wq, Wk, Wv, Wo, pWt);

    // fused QKV projection
    dim3 gblk(256);
    mma_gemm<1,1><<<dim3(3 * D_ / BN, M / BM, 1), gblk, SMEM_DYN>>>(
        pXt, pWt, pBias, nullptr, pQKV, M, 3 * D_, D_, 0, 0, 0, 1.f);

    // grouped conv + LN (8 positions/block, float2 inner loop)
    conv_ln_kernel<<<dim3(S_ / CPOS, B_), dim3(256), CONV_SMEM>>>(x, cw, cb, gamma, beta);

    // V^T per batch (rounded)
    transpose_kernel<<<dim3(D_ / 32, S_ / 32, B_), tb>>>(pV, pVt, S_, D_, sSD, sSD);

    // scores = Q @ K^T * (1/32)
    mma_gemm<0,0><<<dim3(S_ / BN, S_ / BM, B_), gblk, SMEM_DYN>>>(
        pQ, pK, nullptr, nullptr, pS, S_, S_, D_, sSD, sSD, sSS, 0.03125f);

    // softmax rows (rounded probs)
    softmax_kernel<<<dim3(S_, B_), dim3(256)>>>();

    // attn_out = P @ Vt^T = P @ V
    mma_gemm<0,0><<<dim3(D_ / BN, S_ / BM, B_), gblk, SMEM_DYN>>>(
        pS, pVt, nullptr, nullptr, pA, S_, D_, S_, sSS, sSD, sSD, 1.f);

    // combined = LN(conv_ln + attn_out) (rounded)
    add_ln_kernel<<<dim3(S_, B_), dim3(256)>>>(gamma, beta);

    // out = combined @ Wo^T + bo + x (exact residual)
    mma_gemm<0,0><<<dim3(D_ / BN, M / BM, 1), gblk, SMEM_DYN>>>(
        pC, pWt + 3 * DD, bo, x, out, M, D_, D_, 0, 0, 0, 1.f);
}

// round 16
// speedup vs baseline: 2.2734x; 1.2419x over previous
#include <cuda_runtime.h>
#include <math.h>
#include <stdint.h>

#define B_ 4
#define S_ 2048
#define D_ 1024
#define GC_ 64
#define EPS_ 1e-6f

// GEMM tiling (R7-proven config)
#define BM 128
#define BN 128
#define BK 32
#define ST_ 3
#define ASTRIDE 36
#define STAGE_F (2 * 128 * ASTRIDE)
#define STAGE_BYTES (STAGE_F * 4)
#define SMEM_DYN (ST_ * STAGE_BYTES)

// conv_ln v4
#define CPOS 8
#define GPAD 68                                  // padded group stride (floats)
#define XROW (16 * GPAD)                         // 1088 floats per seq row
#define CONV_SMEM (((CPOS + 2) * XROW + 32) * 4)

#define BSD ((size_t)B_ * S_ * D_)

// ---------------- scratch (device globals: allocation-guard safe) ----------------
static __device__ __align__(256) float g_Xt [BSD];
static __device__ __align__(256) float g_QKV[3 * BSD];
static __device__ __align__(256) float g_Vt [BSD];
static __device__ __align__(256) float g_Cv [BSD];
static __device__ __align__(256) float g_Ao [BSD];
static __device__ __align__(256) float g_Sc [(size_t)B_*S_*S_];
static __device__ __align__(256) float g_Wt [(size_t)4*D_*D_];
static __device__ __align__(256) float g_CwT[(size_t)GC_*3*D_];   // repacked conv w [c][k][d]
static __device__ __align__(256) float g_bias[3 * D_];

// ---------------- helpers ----------------
__device__ __forceinline__ uint32_t smem_u32(const void* p) {
    uint32_t a;
    asm("{ .reg .u64 t; cvta.to.shared.u64 t, %1; cvt.u32.u64 %0, t; }" : "=r"(a) : "l"(p));
    return a;
}
__device__ __forceinline__ float to_tf32(float x) {
    uint32_t o;
    asm("cvt.rna.tf32.f32 %0, %1;" : "=r"(o) : "f"(x));
    return __uint_as_float(o);
}
__device__ __forceinline__ void cpa16(uint32_t s, const float* g) {
    asm volatile("cp.async.cg.shared.global [%0], [%1], 16;" :: "r"(s), "l"(g));
}
#define CP_COMMIT() asm volatile("cp.async.commit_group;" ::: "memory")
#define CP_WAIT1()  asm volatile("cp.async.wait_group 1;"  ::: "memory")

__device__ __forceinline__ void ldsm4(uint32_t* r, uint32_t a) {
    asm volatile("ldmatrix.sync.aligned.m8n8.x4.shared.b16 {%0,%1,%2,%3}, [%4];"
        : "=r"(r[0]), "=r"(r[1]), "=r"(r[2]), "=r"(r[3]) : "r"(a));
}
__device__ __forceinline__ void mma_tf32(float* c, const uint32_t* a, const uint32_t* b) {
    asm volatile(
        "mma.sync.aligned.m16n8k8.row.col.f32.tf32.tf32.f32 "
        "{%0,%1,%2,%3}, {%4,%5,%6,%7}, {%8,%9}, {%0,%1,%2,%3};"
        : "+f"(c[0]), "+f"(c[1]), "+f"(c[2]), "+f"(c[3])
        : "r"(a[0]), "r"(a[1]), "r"(a[2]), "r"(a[3]), "r"(b[0]), "r"(b[1]));
}

// ---------------- mma.sync tf32 GEMM (exact R7 config) ----------------
template <int CVT, int SPLIT>
__global__ void __launch_bounds__(256, 2) mma_gemm(
    const float* __restrict__ A, const float* __restrict__ B,
    const float* __restrict__ bias, const float* __restrict__ res,
    float* __restrict__ C, int M, int N, int Kd,
    long long sA, long long sB, long long sC, float alpha)
{
    extern __shared__ __align__(128) float smemf[];
    const uint32_t smem_base = smem_u32(smemf);

    const int t    = threadIdx.x;
    const int wid  = t >> 5;
    const int lane = t & 31;
    const int g    = lane >> 2;
    const int q    = lane & 3;
    const int wm   = wid & 3;
    const int wn   = wid >> 2;
    const int m0 = blockIdx.y * BM, n0 = blockIdx.x * BN;

    const float* Ab = A + (long long)blockIdx.z * sA;
    const float* Bb = B + (long long)blockIdx.z * sB;
    const float* Rb = res ? res + (long long)blockIdx.z * sC : nullptr;

    float acc[2][8][4];
    #pragma unroll
    for (int i = 0; i < 2; i++)
        #pragma unroll
        for (int j = 0; j < 8; j++)
            #pragma unroll
            for (int k = 0; k < 4; k++) acc[i][j][k] = 0.f;

    const int nk = Kd / BK;

    auto load_stage = [&](int j, int s) {
        const int k0 = j * BK;
        const uint32_t sb = smem_base + (uint32_t)s * STAGE_BYTES;
        #pragma unroll
        for (int i = 0; i < 4; i++) {
            int idx = t + i * 256;
            int row = idx >> 3, c4 = idx & 7;
            cpa16(sb + (uint32_t)(row * ASTRIDE + c4 * 4) * 4,
                  Ab + (long long)(m0 + row) * Kd + k0 + c4 * 4);
        }
        #pragma unroll
        for (int i = 0; i < 4; i++) {
            int idx = t + i * 256;
            int row = idx >> 3, c4 = idx & 7;
            cpa16(sb + (uint32_t)(128 * ASTRIDE + row * ASTRIDE + c4 * 4) * 4,
                  Bb + (long long)(n0 + row) * Kd + k0 + c4 * 4);
        }
    };

    load_stage(0, 0); CP_COMMIT();
    load_stage(1, 1); CP_COMMIT();

    const int arow = wm * 32;
    const int bcol = wn * 64;

    const int i8 = lane & 7, qd = lane >> 3;
    uint32_t offA[2], offB[4];
    #pragma unroll
    for (int mf = 0; mf < 2; mf++) {
        int row = arow + mf * 16 + i8 + (qd & 1) * 8;
        offA[mf] = (uint32_t)(row * ASTRIDE + (qd >> 1) * 4) * 4;
    }
    #pragma unroll
    for (int p = 0; p < 4; p++) {
        int row = bcol + p * 16 + i8 + (qd >> 1) * 8;
        offB[p] = (uint32_t)(row * ASTRIDE + (qd & 1) * 4) * 4;
    }

    int s = 0;
    for (int it = 0; it < nk; it++) {
        CP_WAIT1();
        __syncthreads();
        const int j = it + 2;
        if (j < nk) {
            int sn = s + 2; if (sn >= ST_) sn -= ST_;
            load_stage(j, sn);
        }
        CP_COMMIT();

        const uint32_t sAb = smem_base + (uint32_t)s * STAGE_BYTES;
        const uint32_t sBb = sAb + (uint32_t)(128 * ASTRIDE * 4);

        #pragma unroll
        for (int ks = 0; ks < 4; ks++) {
            const uint32_t kb = (uint32_t)(ks * 8 * 4);
            uint32_t a[2][4], b[8][2];
            #pragma unroll
            for (int mf = 0; mf < 2; mf++) ldsm4(a[mf], sAb + offA[mf] + kb);
            #pragma unroll
            for (int p = 0; p < 4; p++) ldsm4(&b[2 * p][0], sBb + offB[p] + kb);
            #pragma unroll
            for (int mf = 0; mf < 2; mf++)
                #pragma unroll
                for (int nf = 0; nf < 8; nf++)
                    mma_tf32(acc[mf][nf], a[mf], b[nf]);
        }
        __syncthreads();
        if (++s == ST_) s = 0;
    }

    // epilogue
    float* Cb;
    int colBase, rowStride;
    if (SPLIT) {
        Cb = C + (long long)(n0 >> 10) * (long long)(B_ * (size_t)S_ * D_);
        colBase = n0 & 1023;
        rowStride = 1024;
    } else {
        Cb = C + (long long)blockIdx.z * sC;
        colBase = n0;
        rowStride = N;
    }

    #pragma unroll
    for (int mf = 0; mf < 2; mf++) {
        #pragma unroll
        for (int nf = 0; nf < 8; nf++) {
            const int row  = m0 + arow + mf * 16 + g;
            const int colG = n0 + bcol + nf * 8 + q * 2;
            const int col  = colBase + bcol + nf * 8 + q * 2;
            float bx = 0.f, by = 0.f;
            if (bias) { bx = bias[colG]; by = bias[colG + 1]; }
            #pragma unroll
            for (int h = 0; h < 2; h++) {
                const int r = row + h * 8;
                float vx = acc[mf][nf][h * 2 + 0] * alpha + bx;
                float vy = acc[mf][nf][h * 2 + 1] * alpha + by;
                if (Rb) {
                    float2 rv = *(const float2*)&Rb[(long long)r * rowStride + col];
                    vx += rv.x; vy += rv.y;
                }
                if (CVT) { vx = to_tf32(vx); vy = to_tf32(vy); }
                float2 v; v.x = vx; v.y = vy;
                *(float2*)&Cb[(long long)r * rowStride + col] = v;
            }
        }
    }
}

// ---------------- convert x -> tf32 + pack bias + repack conv weights ----------------
__global__ void __launch_bounds__(256) convert_pack_kernel(
    const float* __restrict__ in, float* __restrict__ out, int n4,
    const float* __restrict__ bq, const float* __restrict__ bv,
    float* __restrict__ biasOut,
    const float* __restrict__ cw, float* __restrict__ cwT)
{
    int i = blockIdx.x * 256 + threadIdx.x;
    // conv weight repack: cwT[(c*3+k)*D + d] = cw[d*192 + c*3 + k]
    // handled by the last 768 blocks (196608 elems / 256)
    int nConv = GC_ * 3 * D_;          // 196608
    int convBlocks = nConv / 256;      // 768
    if (blockIdx.x >= gridDim.x - convBlocks - 1) {
        if (blockIdx.x == gridDim.x - convBlocks - 1) {
            // pack bias
            for (int k = threadIdx.x; k < 3 * D_; k += 256)
                biasOut[k] = (k < D_) ? bq[k] : ((k < 2 * D_) ? 0.f : bv[k - 2 * D_]);
            return;
        }
        int ci = (blockIdx.x - (gridDim.x - convBlocks)) * 256 + threadIdx.x;
        if (ci < nConv) {
            int d = ci / 192;
            int rem = ci - d * 192;            // c*3 + k
            cwT[(size_t)rem * D_ + d] = cw[ci];
        }
        return;
    }
    if (i < n4) {
        float4 v = ((const float4*)in)[i];
        v.x = to_tf32(v.x); v.y = to_tf32(v.y);
        v.z = to_tf32(v.z); v.w = to_tf32(v.w);
        ((float4*)out)[i] = v;
    }
}

// ---------------- batched weight transpose (4 matrices, one launch) ----------------
__global__ void __launch_bounds__(256) transpose_w4_kernel(
    const float* __restrict__ w0, const float* __restrict__ w1,
    const float* __restrict__ w2, const float* __restrict__ w3,
    float* __restrict__ outBase)
{
    __shared__ float tile[32][33];
    const float* in = (blockIdx.z == 0) ? w0 : (blockIdx.z == 1) ? w1 :
                      (blockIdx.z == 2) ? w2 : w3;
    float* out = outBase + (size_t)blockIdx.z * D_ * D_;
    const int tx = threadIdx.x & 31, ty = threadIdx.x >> 5;
    const int c0 = blockIdx.x * 32, r0 = blockIdx.y * 32;
    #pragma unroll
    for (int j = 0; j < 4; j++)
        tile[ty + j * 8][tx] = in[(long long)(r0 + ty + j * 8) * D_ + c0 + tx];
    __syncthreads();
    #pragma unroll
    for (int j = 0; j < 4; j++)
        out[(long long)(c0 + ty + j * 8) * D_ + r0 + tx] = to_tf32(tile[tx][ty + j * 8]);
}

// ---------------- batched V transpose ----------------
__global__ void __launch_bounds__(256) transpose_kernel(
    const float* __restrict__ in, float* __restrict__ out,
    int R, int C, long long sIn, long long sOut)
{
    __shared__ float tile[32][33];
    in  += (long long)blockIdx.z * sIn;
    out += (long long)blockIdx.z * sOut;
    const int tx = threadIdx.x & 31, ty = threadIdx.x >> 5;
    const int c0 = blockIdx.x * 32, r0 = blockIdx.y * 32;
    #pragma unroll
    for (int j = 0; j < 4; j++)
        tile[ty + j * 8][tx] = in[(long long)(r0 + ty + j * 8) * C + c0 + tx];
    __syncthreads();
    #pragma unroll
    for (int j = 0; j < 4; j++)
        out[(long long)(c0 + ty + j * 8) * R + r0 + tx] = to_tf32(tile[tx][ty + j * 8]);
}

// ---------------- reductions ----------------
__device__ __forceinline__ float warpSum(float v) {
    #pragma unroll
    for (int o = 16; o > 0; o >>= 1) v += __shfl_xor_sync(0xffffffffu, v, o);
    return v;
}
__device__ __forceinline__ float warpMax(float v) {
    #pragma unroll
    for (int o = 16; o > 0; o >>= 1) v = fmaxf(v, __shfl_xor_sync(0xffffffffu, v, o));
    return v;
}
__device__ __forceinline__ float blockSum(float v, float* red) {
    int t = threadIdx.x, lane = t & 31, w = t >> 5;
    v = warpSum(v);
    if (lane == 0) red[w] = v;
    __syncthreads();
    if (w == 0) {
        float x = (lane < 8) ? red[lane] : 0.f;
        x = warpSum(x);
        if (lane == 0) red[0] = x;
    }
    __syncthreads();
    float r = red[0];
    __syncthreads();
    return r;
}
__device__ __forceinline__ float blockMax(float v, float* red) {
    int t = threadIdx.x, lane = t & 31, w = t >> 5;
    v = warpMax(v);
    if (lane == 0) red[w] = v;
    __syncthreads();
    if (w == 0) {
        float x = (lane < 8) ? red[lane] : -1e30f;
        x = warpMax(x);
        if (lane == 0) red[0] = x;
    }
    __syncthreads();
    float r = red[0];
    __syncthreads();
    return r;
}

// ---------------- grouped conv1d + LayerNorm, v4: coalesced repacked weights ----
// CPOS=8 positions/block; weights from cwT[c][k][d] via coalesced float4 loads;
// x rows in group-padded smem (stride GPAD per group) to stagger banks.
__global__ void __launch_bounds__(256, 3) conv_ln_kernel(
    const float* __restrict__ x, const float* __restrict__ cwT,
    const float* __restrict__ cb, const float* __restrict__ gamma,
    const float* __restrict__ beta)
{
    extern __shared__ float cs[];               // xs[(CPOS+2)][XROW] then red[32]
    float* red = cs + (CPOS + 2) * XROW;

    const int t  = threadIdx.x;
    const int s0 = blockIdx.x * CPOS;
    const int b  = blockIdx.y;
    const float* xb = x + (size_t)b * S_ * D_;

    const int d0 = t * 4;
    const int gldC = d0 & 63;                    // column within group (mult of 4)
    const int gldG = d0 >> 6;                    // group id for this thread's float4

    // load CPOS+2 rows into padded smem: element i -> (i>>6)*GPAD + (i&63)
    #pragma unroll
    for (int r = 0; r < CPOS + 2; r++) {
        int sr = s0 - 1 + r;
        float4 v;
        if (sr >= 0 && sr < S_) v = ((const float4*)(xb + (size_t)sr * D_))[t];
        else                    v = make_float4(0.f, 0.f, 0.f, 0.f);
        *(float4*)&cs[r * XROW + gldG * GPAD + gldC] = v;
    }
    __syncthreads();

    const int gb = gldG * GPAD;                  // padded group base for this thread

    float acc[4][CPOS];
    {
        const float4 cbv = *(const float4*)&cb[d0];
        const float cbl[4] = {cbv.x, cbv.y, cbv.z, cbv.w};
        #pragma unroll
        for (int dd = 0; dd < 4; dd++)
            #pragma unroll
            for (int p = 0; p < CPOS; p++) acc[dd][p] = cbl[dd];
    }

    for (int c = 0; c < GC_; c++) {
        float xv[CPOS + 2];
        #pragma unroll
        for (int r = 0; r < CPOS + 2; r++)
            xv[r] = cs[r * XROW + gb + c];
        // coalesced weight loads: [c][k][d0..d0+3]
        const float4 w0 = *(const float4*)&cwT[(size_t)(c * 3 + 0) * D_ + d0];
        const float4 w1 = *(const float4*)&cwT[(size_t)(c * 3 + 1) * D_ + d0];
        const float4 w2 = *(const float4*)&cwT[(size_t)(c * 3 + 2) * D_ + d0];
        #pragma unroll
        for (int p = 0; p < CPOS; p++) {
            acc[0][p] += w0.x * xv[p] + w1.x * xv[p + 1] + w2.x * xv[p + 2];
            acc[1][p] += w0.y * xv[p] + w1.y * xv[p + 1] + w2.y * xv[p + 2];
            acc[2][p] += w0.z * xv[p] + w1.z * xv[p + 1] + w2.z * xv[p + 2];
            acc[3][p] += w0.w * xv[p] + w1.w * xv[p + 1] + w2.w * xv[p + 2];
        }
    }

    const float4 gv  = *(const float4*)&gamma[d0];
    const float4 bvv = *(const float4*)&beta[d0];
    const float gvl[4] = {gv.x, gv.y, gv.z, gv.w};
    const float bvl[4] = {bvv.x, bvv.y, bvv.z, bvv.w};

    for (int p = 0; p < CPOS; p++) {
        float s = acc[0][p] + acc[1][p] + acc[2][p] + acc[3][p];
        float mean = blockSum(s, red) * (1.f / D_);
        float sq = 0.f;
        #pragma unroll
        for (int dd = 0; dd < 4; dd++) { float dl = acc[dd][p] - mean; sq += dl * dl; }
        float var = blockSum(sq, red) * (1.f / (D_ - 1));
        float inv = 1.f / (sqrtf(var) + EPS_);
        float* out = g_Cv + ((size_t)b * S_ + s0 + p) * D_;
        float4 ov;
        ov.x = gvl[0] * (acc[0][p] - mean) * inv + bvl[0];
        ov.y = gvl[1] * (acc[1][p] - mean) * inv + bvl[1];
        ov.z = gvl[2] * (acc[2][p] - mean) * inv + bvl[2];
        ov.w = gvl[3] * (acc[3][p] - mean) * inv + bvl[3];
        *(float4*)&out[d0] = ov;
    }
}

// ---------------- row softmax (writes tf32-rounded probs) ----------------
__global__ void __launch_bounds__(256) softmax_kernel()
{
    __shared__ float red[32];
    const int t = threadIdx.x;
    float* row = g_Sc + ((size_t)blockIdx.y * S_ + blockIdx.x) * S_;

    float v[8];
    float m = -1e30f;
    #pragma unroll
    for (int j = 0; j < 8; j++) { v[j] = row[t + j * 256]; m = fmaxf(m, v[j]); }
    m = blockMax(m, red);

    float sum = 0.f;
    #pragma unroll
    for (int j = 0; j < 8; j++) { v[j] = __expf(v[j] - m); sum += v[j]; }
    sum = blockSum(sum, red);
    float inv = 1.f / sum;
    #pragma unroll
    for (int j = 0; j < 8; j++) row[t + j * 256] = to_tf32(v[j] * inv);
}

// ---------------- combined = LN(conv_ln + attn_out) -> g_Cv (tf32-rounded) ------
__global__ void __launch_bounds__(256) add_ln_kernel(
    const float* __restrict__ gamma, const float* __restrict__ beta)
{
    __shared__ float red[32];
    const int t = threadIdx.x;
    const size_t row = ((size_t)blockIdx.y * S_ + blockIdx.x) * D_;

    float v[4];
    float s = 0.f;
    #pragma unroll
    for (int j = 0; j < 4; j++) {
        int i = t + j * 256;
        v[j] = g_Cv[row + i] + g_Ao[row + i];
        s += v[j];
    }
    float mean = blockSum(s, red) * (1.f / D_);
    float sq = 0.f;
    #pragma unroll
    for (int j = 0; j < 4; j++) { float dl = v[j] - mean; sq += dl * dl; }
    float var = blockSum(sq, red) * (1.f / (D_ - 1));
    float inv = 1.f / (sqrtf(var) + EPS_);
    #pragma unroll
    for (int j = 0; j < 4; j++) {
        int i = t + j * 256;
        g_Cv[row + i] = to_tf32(gamma[i] * (v[j] - mean) * inv + beta[i]);
    }
}

// ---------------- launch ----------------
extern "C" void kernel_launch(void* const* d_in, const int* in_sizes, int n_in,
                              void* d_out, int out_size)
{
    const float* x     = (const float*)d_in[0];
    const float* Wq    = (const float*)d_in[1];
    const float* bq    = (const float*)d_in[2];
    const float* Wk    = (const float*)d_in[3];
    const float* Wv    = (const float*)d_in[4];
    const float* bv    = (const float*)d_in[5];
    const float* cw    = (const float*)d_in[6];
    const float* cb    = (const float*)d_in[7];
    const float* gamma = (const float*)d_in[8];
    const float* beta  = (const float*)d_in[9];
    const float* Wo    = (const float*)d_in[10];
    const float* bo    = (const float*)d_in[11];
    float* out = (float*)d_out;

    float *pXt, *pQKV, *pVt, *pC, *pA, *pS, *pWt, *pCwT, *pBias;
    cudaGetSymbolAddress((void**)&pXt,  g_Xt);
    cudaGetSymbolAddress((void**)&pQKV, g_QKV);
    cudaGetSymbolAddress((void**)&pVt,  g_Vt);
    cudaGetSymbolAddress((void**)&pC,   g_Cv);
    cudaGetSymbolAddress((void**)&pA,   g_Ao);
    cudaGetSymbolAddress((void**)&pS,   g_Sc);
    cudaGetSymbolAddress((void**)&pWt,  g_Wt);
    cudaGetSymbolAddress((void**)&pCwT, g_CwT);
    cudaGetSymbolAddress((void**)&pBias,g_bias);

    cudaFuncSetAttribute(mma_gemm<0,0>, cudaFuncAttributeMaxDynamicSharedMemorySize, SMEM_DYN);
    cudaFuncSetAttribute(mma_gemm<1,0>, cudaFuncAttributeMaxDynamicSharedMemorySize, SMEM_DYN);
    cudaFuncSetAttribute(mma_gemm<1,1>, cudaFuncAttributeMaxDynamicSharedMemorySize, SMEM_DYN);
    cudaFuncSetAttribute(conv_ln_kernel, cudaFuncAttributeMaxDynamicSharedMemorySize, CONV_SMEM);

    const int M = B_ * S_;
    const long long sSD = (long long)S_ * D_;
    const long long sSS = (long long)S_ * S_;
    const long long DD  = (long long)D_ * D_;

    float* pQ = pQKV;
    float* pK = pQKV + BSD;
    float* pV = pQKV + 2 * BSD;

    // tf32-round x + pack bias + repack conv weights (one launch)
    const int n4 = (B_ * S_ * D_) / 4;
    const int convBlocks = (GC_ * 3 * D_) / 256;     // 768
    convert_pack_kernel<<<n4 / 256 + 1 + convBlocks, 256>>>(
        x, pXt, n4, bq, bv, pBias, cw, pCwT);

    // batched GEMM-weight transpose+round
    dim3 tb(256);
    transpose_w4_kernel<<<dim3(D_ / 32, D_ / 32, 4), tb>>>(Wq, Wk, Wv, Wo, pWt);

    // fused QKV projection
    dim3 gblk(256);
    mma_gemm<1,1><<<dim3(3 * D_ / BN, M / BM, 1), gblk, SMEM_DYN>>>(
        pXt, pWt, pBias, nullptr, pQKV, M, 3 * D_, D_, 0, 0, 0, 1.f);

    // grouped conv + LN (repacked coalesced weights)
    conv_ln_kernel<<<dim3(S_ / CPOS, B_), dim3(256), CONV_SMEM>>>(x, pCwT, cb, gamma, beta);

    // V^T per batch (rounded)
    transpose_kernel<<<dim3(D_ / 32, S_ / 32, B_), tb>>>(pV, pVt, S_, D_, sSD, sSD);

    // scores = Q @ K^T * (1/32)
    mma_gemm<0,0><<<dim3(S_ / BN, S_ / BM, B_), gblk, SMEM_DYN>>>(
        pQ, pK, nullptr, nullptr, pS, S_, S_, D_, sSD, sSD, sSS, 0.03125f);

    // softmax rows (rounded probs)
    softmax_kernel<<<dim3(S_, B_), dim3(256)>>>();

    // attn_out = P @ Vt^T = P @ V
    mma_gemm<0,0><<<dim3(D_ / BN, S_ / BM, B_), gblk, SMEM_DYN>>>(
        pS, pVt, nullptr, nullptr, pA, S_, D_, S_, sSS, sSD, sSD, 1.f);

    // combined = LN(conv_ln + attn_out) (rounded)
    add_ln_kernel<<<dim3(S_, B_), dim3(256)>>>(gamma, beta);

    // out = combined @ Wo^T + bo + x (exact residual)
    mma_gemm<0,0><<<dim3(D_ / BN, M / BM, 1), gblk, SMEM_DYN>>>(
        pC, pWt + 3 * DD, bo, x, out, M, D_, D_, 0, 0, 0, 1.f);
}

// round 17
// speedup vs baseline: 2.3722x; 1.0435x over previous
#include <cuda_runtime.h>
#include <math.h>
#include <stdint.h>

#define B_ 4
#define S_ 2048
#define D_ 1024
#define GC_ 64
#define EPS_ 1e-6f

// GEMM tiling (R7-proven config)
#define BM 128
#define BN 128
#define BK 32
#define ST_ 3
#define ASTRIDE 36
#define STAGE_F (2 * 128 * ASTRIDE)
#define STAGE_BYTES (STAGE_F * 4)
#define SMEM_DYN (ST_ * STAGE_BYTES)

// conv_ln v4
#define CPOS 8
#define GPAD 68
#define XROW (16 * GPAD)
#define CONV_SMEM (((CPOS + 2) * XROW + 32) * 4)

// fused QKV+conv launch
#define QKV_BLOCKS 1536                 // (3*D/BN) * (B*S/BM) = 24*64
#define CONV_BLOCKS 1024                // (S/CPOS) * B
#define FUSED_SMEM (SMEM_DYN > CONV_SMEM ? SMEM_DYN : CONV_SMEM)

#define BSD ((size_t)B_ * S_ * D_)

// ---------------- scratch (device globals: allocation-guard safe) ----------------
static __device__ __align__(256) float g_Xt [BSD];
static __device__ __align__(256) float g_QKV[3 * BSD];
static __device__ __align__(256) float g_Vt [BSD];
static __device__ __align__(256) float g_Cv [BSD];
static __device__ __align__(256) float g_Ao [BSD];
static __device__ __align__(256) float g_Sc [(size_t)B_*S_*S_];
static __device__ __align__(256) float g_Wt [(size_t)4*D_*D_];
static __device__ __align__(256) float g_CwT[(size_t)GC_*3*D_];
static __device__ __align__(256) float g_bias[3 * D_];

// ---------------- helpers ----------------
__device__ __forceinline__ uint32_t smem_u32(const void* p) {
    uint32_t a;
    asm("{ .reg .u64 t; cvta.to.shared.u64 t, %1; cvt.u32.u64 %0, t; }" : "=r"(a) : "l"(p));
    return a;
}
__device__ __forceinline__ float to_tf32(float x) {
    uint32_t o;
    asm("cvt.rna.tf32.f32 %0, %1;" : "=r"(o) : "f"(x));
    return __uint_as_float(o);
}
__device__ __forceinline__ void cpa16(uint32_t s, const float* g) {
    asm volatile("cp.async.cg.shared.global [%0], [%1], 16;" :: "r"(s), "l"(g));
}
#define CP_COMMIT() asm volatile("cp.async.commit_group;" ::: "memory")
#define CP_WAIT1()  asm volatile("cp.async.wait_group 1;"  ::: "memory")

__device__ __forceinline__ void ldsm4(uint32_t* r, uint32_t a) {
    asm volatile("ldmatrix.sync.aligned.m8n8.x4.shared.b16 {%0,%1,%2,%3}, [%4];"
        : "=r"(r[0]), "=r"(r[1]), "=r"(r[2]), "=r"(r[3]) : "r"(a));
}
__device__ __forceinline__ void mma_tf32(float* c, const uint32_t* a, const uint32_t* b) {
    asm volatile(
        "mma.sync.aligned.m16n8k8.row.col.f32.tf32.tf32.f32 "
        "{%0,%1,%2,%3}, {%4,%5,%6,%7}, {%8,%9}, {%0,%1,%2,%3};"
        : "+f"(c[0]), "+f"(c[1]), "+f"(c[2]), "+f"(c[3])
        : "r"(a[0]), "r"(a[1]), "r"(a[2]), "r"(a[3]), "r"(b[0]), "r"(b[1]));
}

// ---------------- reductions ----------------
__device__ __forceinline__ float warpSum(float v) {
    #pragma unroll
    for (int o = 16; o > 0; o >>= 1) v += __shfl_xor_sync(0xffffffffu, v, o);
    return v;
}
__device__ __forceinline__ float warpMax(float v) {
    #pragma unroll
    for (int o = 16; o > 0; o >>= 1) v = fmaxf(v, __shfl_xor_sync(0xffffffffu, v, o));
    return v;
}
__device__ __forceinline__ float blockSum(float v, float* red) {
    int t = threadIdx.x, lane = t & 31, w = t >> 5;
    v = warpSum(v);
    if (lane == 0) red[w] = v;
    __syncthreads();
    if (w == 0) {
        float x = (lane < 8) ? red[lane] : 0.f;
        x = warpSum(x);
        if (lane == 0) red[0] = x;
    }
    __syncthreads();
    float r = red[0];
    __syncthreads();
    return r;
}
__device__ __forceinline__ float blockMax(float v, float* red) {
    int t = threadIdx.x, lane = t & 31, w = t >> 5;
    v = warpMax(v);
    if (lane == 0) red[w] = v;
    __syncthreads();
    if (w == 0) {
        float x = (lane < 8) ? red[lane] : -1e30f;
        x = warpMax(x);
        if (lane == 0) red[0] = x;
    }
    __syncthreads();
    float r = red[0];
    __syncthreads();
    return r;
}

// ---------------- GEMM body (device function; R7 config) ----------------
// A [M,K], B [N,K] row-major tf32. bias always non-null here when BIAS=1.
template <int CVT, int SPLIT, int BIAS, int RES>
__device__ __forceinline__ void gemm_body(
    float* smemf, int bx, int by, int bz,
    const float* __restrict__ A, const float* __restrict__ B,
    const float* __restrict__ bias, const float* __restrict__ res,
    float* __restrict__ C, int M, int N, int Kd,
    long long sA, long long sB, long long sC, float alpha)
{
    const uint32_t smem_base = smem_u32(smemf);
    const int t    = threadIdx.x;
    const int wid  = t >> 5;
    const int lane = t & 31;
    const int g    = lane >> 2;
    const int q    = lane & 3;
    const int wm   = wid & 3;
    const int wn   = wid >> 2;
    const int m0 = by * BM, n0 = bx * BN;

    const float* Ab = A + (long long)bz * sA;
    const float* Bb = B + (long long)bz * sB;
    const float* Rb = RES ? res + (long long)bz * sC : nullptr;

    float acc[2][8][4];
    #pragma unroll
    for (int i = 0; i < 2; i++)
        #pragma unroll
        for (int j = 0; j < 8; j++)
            #pragma unroll
            for (int k = 0; k < 4; k++) acc[i][j][k] = 0.f;

    const int nk = Kd / BK;

    auto load_stage = [&](int j, int s) {
        const int k0 = j * BK;
        const uint32_t sb = smem_base + (uint32_t)s * STAGE_BYTES;
        #pragma unroll
        for (int i = 0; i < 4; i++) {
            int idx = t + i * 256;
            int row = idx >> 3, c4 = idx & 7;
            cpa16(sb + (uint32_t)(row * ASTRIDE + c4 * 4) * 4,
                  Ab + (long long)(m0 + row) * Kd + k0 + c4 * 4);
        }
        #pragma unroll
        for (int i = 0; i < 4; i++) {
            int idx = t + i * 256;
            int row = idx >> 3, c4 = idx & 7;
            cpa16(sb + (uint32_t)(128 * ASTRIDE + row * ASTRIDE + c4 * 4) * 4,
                  Bb + (long long)(n0 + row) * Kd + k0 + c4 * 4);
        }
    };

    load_stage(0, 0); CP_COMMIT();
    load_stage(1, 1); CP_COMMIT();

    const int arow = wm * 32;
    const int bcol = wn * 64;

    const int i8 = lane & 7, qd = lane >> 3;
    uint32_t offA[2], offB[4];
    #pragma unroll
    for (int mf = 0; mf < 2; mf++) {
        int row = arow + mf * 16 + i8 + (qd & 1) * 8;
        offA[mf] = (uint32_t)(row * ASTRIDE + (qd >> 1) * 4) * 4;
    }
    #pragma unroll
    for (int p = 0; p < 4; p++) {
        int row = bcol + p * 16 + i8 + (qd >> 1) * 8;
        offB[p] = (uint32_t)(row * ASTRIDE + (qd & 1) * 4) * 4;
    }

    int s = 0;
    for (int it = 0; it < nk; it++) {
        CP_WAIT1();
        __syncthreads();
        const int j = it + 2;
        if (j < nk) {
            int sn = s + 2; if (sn >= ST_) sn -= ST_;
            load_stage(j, sn);
        }
        CP_COMMIT();

        const uint32_t sAb = smem_base + (uint32_t)s * STAGE_BYTES;
        const uint32_t sBb = sAb + (uint32_t)(128 * ASTRIDE * 4);

        #pragma unroll
        for (int ks = 0; ks < 4; ks++) {
            const uint32_t kb = (uint32_t)(ks * 8 * 4);
            uint32_t a[2][4], b[8][2];
            #pragma unroll
            for (int mf = 0; mf < 2; mf++) ldsm4(a[mf], sAb + offA[mf] + kb);
            #pragma unroll
            for (int p = 0; p < 4; p++) ldsm4(&b[2 * p][0], sBb + offB[p] + kb);
            #pragma unroll
            for (int mf = 0; mf < 2; mf++)
                #pragma unroll
                for (int nf = 0; nf < 8; nf++)
                    mma_tf32(acc[mf][nf], a[mf], b[nf]);
        }
        __syncthreads();
        if (++s == ST_) s = 0;
    }

    float* Cb;
    int colBase, rowStride;
    if (SPLIT) {
        Cb = C + (long long)(n0 >> 10) * (long long)BSD;
        colBase = n0 & 1023;
        rowStride = 1024;
    } else {
        Cb = C + (long long)bz * sC;
        colBase = n0;
        rowStride = N;
    }

    #pragma unroll
    for (int mf = 0; mf < 2; mf++) {
        #pragma unroll
        for (int nf = 0; nf < 8; nf++) {
            const int row  = m0 + arow + mf * 16 + g;
            const int colG = n0 + bcol + nf * 8 + q * 2;
            const int col  = colBase + bcol + nf * 8 + q * 2;
            float bx2 = 0.f, by2 = 0.f;
            if (BIAS) { bx2 = bias[colG]; by2 = bias[colG + 1]; }
            #pragma unroll
            for (int h = 0; h < 2; h++) {
                const int r = row + h * 8;
                float vx = acc[mf][nf][h * 2 + 0] * alpha + bx2;
                float vy = acc[mf][nf][h * 2 + 1] * alpha + by2;
                if (RES) {
                    float2 rv = *(const float2*)&Rb[(long long)r * rowStride + col];
                    vx += rv.x; vy += rv.y;
                }
                if (CVT) { vx = to_tf32(vx); vy = to_tf32(vy); }
                float2 v; v.x = vx; v.y = vy;
                *(float2*)&Cb[(long long)r * rowStride + col] = v;
            }
        }
    }
}

// ---------------- conv+LN body (device function; v4) ----------------
__device__ __forceinline__ void conv_body(
    float* cs, int blk, int b,
    const float* __restrict__ x, const float* __restrict__ cwT,
    const float* __restrict__ cb, const float* __restrict__ gamma,
    const float* __restrict__ beta)
{
    float* red = cs + (CPOS + 2) * XROW;
    const int t  = threadIdx.x;
    const int s0 = blk * CPOS;
    const float* xb = x + (size_t)b * S_ * D_;

    const int d0 = t * 4;
    const int gldC = d0 & 63;
    const int gldG = d0 >> 6;

    #pragma unroll
    for (int r = 0; r < CPOS + 2; r++) {
        int sr = s0 - 1 + r;
        float4 v;
        if (sr >= 0 && sr < S_) v = ((const float4*)(xb + (size_t)sr * D_))[t];
        else                    v = make_float4(0.f, 0.f, 0.f, 0.f);
        *(float4*)&cs[r * XROW + gldG * GPAD + gldC] = v;
    }
    __syncthreads();

    const int gb = gldG * GPAD;

    float acc[4][CPOS];
    {
        const float4 cbv = *(const float4*)&cb[d0];
        const float cbl[4] = {cbv.x, cbv.y, cbv.z, cbv.w};
        #pragma unroll
        for (int dd = 0; dd < 4; dd++)
            #pragma unroll
            for (int p = 0; p < CPOS; p++) acc[dd][p] = cbl[dd];
    }

    for (int c = 0; c < GC_; c++) {
        float xv[CPOS + 2];
        #pragma unroll
        for (int r = 0; r < CPOS + 2; r++)
            xv[r] = cs[r * XROW + gb + c];
        const float4 w0 = *(const float4*)&cwT[(size_t)(c * 3 + 0) * D_ + d0];
        const float4 w1 = *(const float4*)&cwT[(size_t)(c * 3 + 1) * D_ + d0];
        const float4 w2 = *(const float4*)&cwT[(size_t)(c * 3 + 2) * D_ + d0];
        #pragma unroll
        for (int p = 0; p < CPOS; p++) {
            acc[0][p] += w0.x * xv[p] + w1.x * xv[p + 1] + w2.x * xv[p + 2];
            acc[1][p] += w0.y * xv[p] + w1.y * xv[p + 1] + w2.y * xv[p + 2];
            acc[2][p] += w0.z * xv[p] + w1.z * xv[p + 1] + w2.z * xv[p + 2];
            acc[3][p] += w0.w * xv[p] + w1.w * xv[p + 1] + w2.w * xv[p + 2];
        }
    }

    const float4 gv  = *(const float4*)&gamma[d0];
    const float4 bvv = *(const float4*)&beta[d0];
    const float gvl[4] = {gv.x, gv.y, gv.z, gv.w};
    const float bvl[4] = {bvv.x, bvv.y, bvv.z, bvv.w};

    for (int p = 0; p < CPOS; p++) {
        float s = acc[0][p] + acc[1][p] + acc[2][p] + acc[3][p];
        float mean = blockSum(s, red) * (1.f / D_);
        float sq = 0.f;
        #pragma unroll
        for (int dd = 0; dd < 4; dd++) { float dl = acc[dd][p] - mean; sq += dl * dl; }
        float var = blockSum(sq, red) * (1.f / (D_ - 1));
        float inv = 1.f / (sqrtf(var) + EPS_);
        float* out = g_Cv + ((size_t)b * S_ + s0 + p) * D_;
        float4 ov;
        ov.x = gvl[0] * (acc[0][p] - mean) * inv + bvl[0];
        ov.y = gvl[1] * (acc[1][p] - mean) * inv + bvl[1];
        ov.z = gvl[2] * (acc[2][p] - mean) * inv + bvl[2];
        ov.w = gvl[3] * (acc[3][p] - mean) * inv + bvl[3];
        *(float4*)&out[d0] = ov;
    }
}

// ---------------- fused QKV GEMM + conv_ln (heterogeneous grid) ----------------
__global__ void __launch_bounds__(256, 2) qkv_conv_kernel(
    const float* __restrict__ Xt, const float* __restrict__ Wt,
    const float* __restrict__ bias, float* __restrict__ QKV,
    const float* __restrict__ x, const float* __restrict__ cwT,
    const float* __restrict__ cb, const float* __restrict__ gamma,
    const float* __restrict__ beta)
{
    extern __shared__ float smemf[];
    const int gx = blockIdx.x;
    if (gx < QKV_BLOCKS) {
        gemm_body<1, 1, 1, 0>(smemf, gx % 24, gx / 24, 0,
            Xt, Wt, bias, nullptr, QKV, B_ * S_, 3 * D_, D_, 0, 0, 0, 1.f);
    } else {
        const int i = gx - QKV_BLOCKS;
        conv_body(smemf, i & 255, i >> 8, x, cwT, cb, gamma, beta);
    }
}

// ---------------- standalone GEMM (other 3 GEMMs) ----------------
template <int CVT, int SPLIT, int BIAS, int RES>
__global__ void __launch_bounds__(256, 2) mma_gemm(
    const float* __restrict__ A, const float* __restrict__ B,
    const float* __restrict__ bias, const float* __restrict__ res,
    float* __restrict__ C, int M, int N, int Kd,
    long long sA, long long sB, long long sC, float alpha)
{
    extern __shared__ float smemf[];
    gemm_body<CVT, SPLIT, BIAS, RES>(smemf, blockIdx.x, blockIdx.y, blockIdx.z,
        A, B, bias, res, C, M, N, Kd, sA, sB, sC, alpha);
}

// ---------------- convert x -> tf32 + pack bias + repack conv weights ----------------
__global__ void __launch_bounds__(256) convert_pack_kernel(
    const float* __restrict__ in, float* __restrict__ out, int n4,
    const float* __restrict__ bq, const float* __restrict__ bv,
    float* __restrict__ biasOut,
    const float* __restrict__ cw, float* __restrict__ cwT)
{
    int i = blockIdx.x * 256 + threadIdx.x;
    int nConv = GC_ * 3 * D_;
    int convBlocks = nConv / 256;
    if (blockIdx.x >= gridDim.x - convBlocks - 1) {
        if (blockIdx.x == gridDim.x - convBlocks - 1) {
            for (int k = threadIdx.x; k < 3 * D_; k += 256)
                biasOut[k] = (k < D_) ? bq[k] : ((k < 2 * D_) ? 0.f : bv[k - 2 * D_]);
            return;
        }
        int ci = (blockIdx.x - (gridDim.x - convBlocks)) * 256 + threadIdx.x;
        if (ci < nConv) {
            int d = ci / 192;
            int rem = ci - d * 192;
            cwT[(size_t)rem * D_ + d] = cw[ci];
        }
        return;
    }
    if (i < n4) {
        float4 v = ((const float4*)in)[i];
        v.x = to_tf32(v.x); v.y = to_tf32(v.y);
        v.z = to_tf32(v.z); v.w = to_tf32(v.w);
        ((float4*)out)[i] = v;
    }
}

// ---------------- batched weight transpose ----------------
__global__ void __launch_bounds__(256) transpose_w4_kernel(
    const float* __restrict__ w0, const float* __restrict__ w1,
    const float* __restrict__ w2, const float* __restrict__ w3,
    float* __restrict__ outBase)
{
    __shared__ float tile[32][33];
    const float* in = (blockIdx.z == 0) ? w0 : (blockIdx.z == 1) ? w1 :
                      (blockIdx.z == 2) ? w2 : w3;
    float* out = outBase + (size_t)blockIdx.z * D_ * D_;
    const int tx = threadIdx.x & 31, ty = threadIdx.x >> 5;
    const int c0 = blockIdx.x * 32, r0 = blockIdx.y * 32;
    #pragma unroll
    for (int j = 0; j < 4; j++)
        tile[ty + j * 8][tx] = in[(long long)(r0 + ty + j * 8) * D_ + c0 + tx];
    __syncthreads();
    #pragma unroll
    for (int j = 0; j < 4; j++)
        out[(long long)(c0 + ty + j * 8) * D_ + r0 + tx] = to_tf32(tile[tx][ty + j * 8]);
}

// ---------------- batched V transpose ----------------
__global__ void __launch_bounds__(256) transpose_kernel(
    const float* __restrict__ in, float* __restrict__ out,
    int R, int C, long long sIn, long long sOut)
{
    __shared__ float tile[32][33];
    in  += (long long)blockIdx.z * sIn;
    out += (long long)blockIdx.z * sOut;
    const int tx = threadIdx.x & 31, ty = threadIdx.x >> 5;
    const int c0 = blockIdx.x * 32, r0 = blockIdx.y * 32;
    #pragma unroll
    for (int j = 0; j < 4; j++)
        tile[ty + j * 8][tx] = in[(long long)(r0 + ty + j * 8) * C + c0 + tx];
    __syncthreads();
    #pragma unroll
    for (int j = 0; j < 4; j++)
        out[(long long)(c0 + ty + j * 8) * R + r0 + tx] = to_tf32(tile[tx][ty + j * 8]);
}

// ---------------- row softmax ----------------
__global__ void __launch_bounds__(256) softmax_kernel()
{
    __shared__ float red[32];
    const int t = threadIdx.x;
    float* row = g_Sc + ((size_t)blockIdx.y * S_ + blockIdx.x) * S_;

    float v[8];
    float m = -1e30f;
    #pragma unroll
    for (int j = 0; j < 8; j++) { v[j] = row[t + j * 256]; m = fmaxf(m, v[j]); }
    m = blockMax(m, red);

    float sum = 0.f;
    #pragma unroll
    for (int j = 0; j < 8; j++) { v[j] = __expf(v[j] - m); sum += v[j]; }
    sum = blockSum(sum, red);
    float inv = 1.f / sum;
    #pragma unroll
    for (int j = 0; j < 8; j++) row[t + j * 256] = to_tf32(v[j] * inv);
}

// ---------------- combined = LN(conv_ln + attn_out) ----------------
__global__ void __launch_bounds__(256) add_ln_kernel(
    const float* __restrict__ gamma, const float* __restrict__ beta)
{
    __shared__ float red[32];
    const int t = threadIdx.x;
    const size_t row = ((size_t)blockIdx.y * S_ + blockIdx.x) * D_;

    float v[4];
    float s = 0.f;
    #pragma unroll
    for (int j = 0; j < 4; j++) {
        int i = t + j * 256;
        v[j] = g_Cv[row + i] + g_Ao[row + i];
        s += v[j];
    }
    float mean = blockSum(s, red) * (1.f / D_);
    float sq = 0.f;
    #pragma unroll
    for (int j = 0; j < 4; j++) { float dl = v[j] - mean; sq += dl * dl; }
    float var = blockSum(sq, red) * (1.f / (D_ - 1));
    float inv = 1.f / (sqrtf(var) + EPS_);
    #pragma unroll
    for (int j = 0; j < 4; j++) {
        int i = t + j * 256;
        g_Cv[row + i] = to_tf32(gamma[i] * (v[j] - mean) * inv + beta[i]);
    }
}

// ---------------- launch ----------------
extern "C" void kernel_launch(void* const* d_in, const int* in_sizes, int n_in,
                              void* d_out, int out_size)
{
    const float* x     = (const float*)d_in[0];
    const float* Wq    = (const float*)d_in[1];
    const float* bq    = (const float*)d_in[2];
    const float* Wk    = (const float*)d_in[3];
    const float* Wv    = (const float*)d_in[4];
    const float* bv    = (const float*)d_in[5];
    const float* cw    = (const float*)d_in[6];
    const float* cb    = (const float*)d_in[7];
    const float* gamma = (const float*)d_in[8];
    const float* beta  = (const float*)d_in[9];
    const float* Wo    = (const float*)d_in[10];
    const float* bo    = (const float*)d_in[11];
    float* out = (float*)d_out;

    float *pXt, *pQKV, *pVt, *pC, *pA, *pS, *pWt, *pCwT, *pBias;
    cudaGetSymbolAddress((void**)&pXt,  g_Xt);
    cudaGetSymbolAddress((void**)&pQKV, g_QKV);
    cudaGetSymbolAddress((void**)&pVt,  g_Vt);
    cudaGetSymbolAddress((void**)&pC,   g_Cv);
    cudaGetSymbolAddress((void**)&pA,   g_Ao);
    cudaGetSymbolAddress((void**)&pS,   g_Sc);
    cudaGetSymbolAddress((void**)&pWt,  g_Wt);
    cudaGetSymbolAddress((void**)&pCwT, g_CwT);
    cudaGetSymbolAddress((void**)&pBias,g_bias);

    cudaFuncSetAttribute(qkv_conv_kernel, cudaFuncAttributeMaxDynamicSharedMemorySize, FUSED_SMEM);
    cudaFuncSetAttribute(mma_gemm<0,0,0,0>, cudaFuncAttributeMaxDynamicSharedMemorySize, SMEM_DYN);
    cudaFuncSetAttribute(mma_gemm<0,0,1,1>, cudaFuncAttributeMaxDynamicSharedMemorySize, SMEM_DYN);

    const int M = B_ * S_;
    const long long sSD = (long long)S_ * D_;
    const long long sSS = (long long)S_ * S_;
    const long long DD  = (long long)D_ * D_;

    float* pQ = pQKV;
    float* pK = pQKV + BSD;
    float* pV = pQKV + 2 * BSD;

    // tf32-round x + pack bias + repack conv weights
    const int n4 = (B_ * S_ * D_) / 4;
    const int convBlocks = (GC_ * 3 * D_) / 256;
    convert_pack_kernel<<<n4 / 256 + 1 + convBlocks, 256>>>(
        x, pXt, n4, bq, bv, pBias, cw, pCwT);

    // batched GEMM-weight transpose+round
    dim3 tb(256);
    transpose_w4_kernel<<<dim3(D_ / 32, D_ / 32, 4), tb>>>(Wq, Wk, Wv, Wo, pWt);

    // fused QKV GEMM + conv_ln (tensor + fma pipes overlap)
    qkv_conv_kernel<<<QKV_BLOCKS + CONV_BLOCKS, 256, FUSED_SMEM>>>(
        pXt, pWt, pBias, pQKV, x, pCwT, cb, gamma, beta);

    // V^T per batch
    transpose_kernel<<<dim3(D_ / 32, S_ / 32, B_), tb>>>(pV, pVt, S_, D_, sSD, sSD);

    // scores = Q @ K^T * (1/32)
    mma_gemm<0,0,0,0><<<dim3(S_ / BN, S_ / BM, B_), 256, SMEM_DYN>>>(
        pQ, pK, nullptr, nullptr, pS, S_, S_, D_, sSD, sSD, sSS, 0.03125f);

    // softmax rows
    softmax_kernel<<<dim3(S_, B_), 256>>>();

    // attn_out = P @ Vt^T
    mma_gemm<0,0,0,0><<<dim3(D_ / BN, S_ / BM, B_), 256, SMEM_DYN>>>(
        pS, pVt, nullptr, nullptr, pA, S_, D_, S_, sSS, sSD, sSD, 1.f);

    // combined = LN(conv_ln + attn_out)
    add_ln_kernel<<<dim3(S_, B_), 256>>>(gamma, beta);

    // out = combined @ Wo^T + bo + x
    mma_gemm<0,0,1,1><<<dim3(D_ / BN, M / BM, 1), 256, SMEM_DYN>>>(
        pC, pWt + 3 * DD, bo, x, out, M, D_, D_, 0, 0, 0, 1.f);
}